// round 13
// baseline (speedup 1.0000x reference)
#include <cuda_runtime.h>
#include <cuda_fp16.h>
#include <cstdint>

#define BB 16384
#define DD 256
#define HH 1024
#define EE 8
#define KXT 257   // D+1
#define TOPK 2

// ---------------- scratch (static device memory; no allocations) -------------
__device__ float  g_h[(size_t)BB * HH];          // router hidden (fp32, exact)
__device__ __half g_w1k[(size_t)EE * KXT * HH];  // fc1 W half, K-major (same layout as Ew1)
__device__ __half g_w2k[(size_t)EE * HH * HH];   // fc2 W half, K-major
__device__ __half g_w3k[(size_t)EE * HH * DD];   // fc3 W half, K-major
__device__ __half g_h1[(size_t)2 * BB * HH];     // expert fc1 out (half)
__device__ __half g_h2[(size_t)2 * BB * HH];     // expert fc2 out (half)
__device__ float  g_eout[(size_t)2 * BB * DD];   // scaled expert out (fp32)
__device__ int    g_perm[2 * BB];
__device__ float  g_wgt[2 * BB];
__device__ int    g_slot[2 * BB];
__device__ int    g_topk_idx[BB * TOPK];
__device__ float  g_topk_a[BB * TOPK];
__device__ int    g_cnt[EE];
__device__ int    g_off[EE];
__device__ int    g_cursor[EE];

__device__ __forceinline__ float silu_precise(float v) {
    return v / (1.f + expf(-v));
}

__device__ __forceinline__ __half h_lo(uint32_t w) {
    return __ushort_as_half((unsigned short)(w & 0xFFFFu));
}
__device__ __forceinline__ __half h_hi(uint32_t w) {
    return __ushort_as_half((unsigned short)(w >> 16));
}

__device__ __forceinline__ void mma_f16(float* d, const unsigned* a, const unsigned* b) {
    asm volatile(
        "mma.sync.aligned.m16n8k16.row.col.f32.f16.f16.f32 "
        "{%0,%1,%2,%3}, {%4,%5,%6,%7}, {%8,%9}, {%0,%1,%2,%3};"
        : "+f"(d[0]), "+f"(d[1]), "+f"(d[2]), "+f"(d[3])
        : "r"(a[0]), "r"(a[1]), "r"(a[2]), "r"(a[3]), "r"(b[0]), "r"(b[1]));
}

// ---------------- reset ------------------------------------------------------
__global__ void reset_kernel() {
    if (threadIdx.x < EE) g_cnt[threadIdx.x] = 0;
}

// ---------------- pre-pass: ELEMENTWISE fp32->fp16 weight cast ---------------
__global__ __launch_bounds__(256)
void cast_w_kernel(const float* __restrict__ W, __half* __restrict__ Wh, int n4)
{
    const int i = blockIdx.x * 256 + threadIdx.x;
    if (i >= n4) return;
    const float4 v = ((const float4*)W)[i];
    ((__half2*)Wh)[i * 2]     = __floats2half2_rn(v.x, v.y);
    ((__half2*)Wh)[i * 2 + 1] = __floats2half2_rn(v.z, v.w);
}

// ---------------- fp32 router GEMM (exact; gating must match reference) ------
__global__ __launch_bounds__(256)
void router_gemm_kernel(const float* __restrict__ X, const float* __restrict__ T,
                        const float* __restrict__ W, const float* __restrict__ Bias)
{
    constexpr int KK = KXT, NN = HH;
    constexpr int BM = 128, BN = 128, BK = 8;
    constexpr int NKT = (KK + BK - 1) / BK;

    const int row0 = blockIdx.y * BM;
    const int col0 = blockIdx.x * BN;

    __shared__ __align__(16) float As[BK][BM + 4];
    __shared__ __align__(16) float Bs[BK][BN + 4];

    const int tid = threadIdx.x;
    const int tx = tid & 15;
    const int ty = tid >> 4;
    const int a_row = tid >> 1;
    const int a_k4  = (tid & 1) * 4;
    const int b_k  = tid >> 5;
    const int b_n  = (tid & 31) * 4;

    const int tok = row0 + a_row;

    float acc[8][8];
    #pragma unroll
    for (int i = 0; i < 8; i++)
        #pragma unroll
        for (int j = 0; j < 8; j++) acc[i][j] = 0.f;

    for (int kt = 0; kt < NKT; kt++) {
        const int kb = kt * BK;
        #pragma unroll
        for (int l = 0; l < 4; l++) {
            const int k = kb + a_k4 + l;
            float v = 0.f;
            if (k < DD)       v = X[(size_t)tok * DD + k];
            else if (k == DD) v = T[tok];
            As[a_k4 + l][a_row] = v;
        }
        {
            const int k = kb + b_k;
            float4 v = make_float4(0.f, 0.f, 0.f, 0.f);
            if (k < KK) v = *(const float4*)(W + (size_t)k * NN + col0 + b_n);
            Bs[b_k][b_n + 0] = v.x;
            Bs[b_k][b_n + 1] = v.y;
            Bs[b_k][b_n + 2] = v.z;
            Bs[b_k][b_n + 3] = v.w;
        }
        __syncthreads();
        #pragma unroll
        for (int k = 0; k < BK; k++) {
            float a[8], b[8];
            *(float4*)(a)     = *(const float4*)&As[k][ty * 8];
            *(float4*)(a + 4) = *(const float4*)&As[k][ty * 8 + 4];
            *(float4*)(b)     = *(const float4*)&Bs[k][tx * 8];
            *(float4*)(b + 4) = *(const float4*)&Bs[k][tx * 8 + 4];
            #pragma unroll
            for (int i = 0; i < 8; i++)
                #pragma unroll
                for (int j = 0; j < 8; j++)
                    acc[i][j] = fmaf(a[i], b[j], acc[i][j]);
        }
        __syncthreads();
    }

    float bias[8];
    #pragma unroll
    for (int j = 0; j < 8; j++) bias[j] = Bias[col0 + tx * 8 + j];

    #pragma unroll
    for (int i = 0; i < 8; i++) {
        const int rloc = row0 + ty * 8 + i;
        float* dst = g_h + (size_t)rloc * HH;
        float tmp[8];
        #pragma unroll
        for (int j = 0; j < 8; j++)
            tmp[j] = silu_precise(acc[i][j] + bias[j]);
        *(float4*)(dst + col0 + tx * 8)     = make_float4(tmp[0], tmp[1], tmp[2], tmp[3]);
        *(float4*)(dst + col0 + tx * 8 + 4) = make_float4(tmp[4], tmp[5], tmp[6], tmp[7]);
    }
}

// ---------------- FP16 tensor-core grouped GEMM (R4 structure, half-B feed) --
// Identical to the PASSING R12 kernel except store_b: halves are extracted
// from the uint4 prefetch registers via named members + shift/mask (constant
// indices, no address-of) so the prefetch stays in registers — R12's pointer
// cast demoted it to local memory and tripled the mainloop time.
// MODE 1: fc1 : A = [x|t] gathered by g_perm (K=257),  W=g_w1k, silu  -> g_h1
// MODE 2: fc2 : A = g_h1 (K=1024),                     W=g_w2k, silu  -> g_h2
// MODE 3: fc3 : A = g_h2 (K=1024),                     W=g_w3k, *alpha-> g_eout
template <int MODE>
__global__ __launch_bounds__(256)
void hgemm_kernel(const float* __restrict__ X, const float* __restrict__ T,
                  const __half* __restrict__ W, const float* __restrict__ Bias)
{
    constexpr int KK = (MODE == 1) ? KXT : HH;
    constexpr int NN = (MODE == 3) ? DD : HH;
    constexpr int BM = 128, BN = 128, BK = 32;
    constexpr int RS = BK + 8;                 // 40 halves
    constexpr int NKT = (KK + BK - 1) / BK;

    const int e = blockIdx.z;
    const int m_base  = g_off[e];
    const int m_count = g_cnt[e];
    const int row0 = blockIdx.y * BM;
    if (row0 >= m_count) return;
    const int col0 = blockIdx.x * BN;

    const __half* __restrict__ Wp = W + (size_t)e * KK * NN;
    const float* __restrict__ Bp = Bias + (size_t)e * NN;

    __shared__ __align__(16) __half As[2][BM * RS];
    __shared__ __align__(16) __half Bs[2][BN * RS];

    const int tid  = threadIdx.x;
    const int warp = tid >> 5;
    const int lane = tid & 31;
    const int wm = warp >> 2;       // 0..1 : 64-row slab
    const int wn = warp & 3;        // 0..3 : 32-col slab
    const int r  = lane >> 2;       // 0..7
    const int c  = lane & 3;        // 0..3

    // A loader: thread -> (row a_m, 16 consecutive k halves)
    const int a_m = tid >> 1;              // 0..127
    const int a_k = (tid & 1) * 16;        // 0 or 16
    const bool a_valid = (row0 + a_m) < m_count;
    int tok = 0;
    const __half* __restrict__ Arow = nullptr;
    if (MODE == 1) {
        if (a_valid) tok = g_perm[m_base + row0 + a_m];
    } else {
        const __half* src = (MODE == 2) ? g_h1 : g_h2;
        Arow = src + (size_t)(m_base + row0 + a_m) * KK;
    }

    // B loader: thread -> (k = b_kk, 16 consecutive n)
    const int b_kk = tid >> 3;             // 0..31
    const int b_n0 = (tid & 7) * 16;       // 0..112

    float acc[4][4][4];
    #pragma unroll
    for (int mi = 0; mi < 4; mi++)
        #pragma unroll
        for (int ni = 0; ni < 4; ni++)
            #pragma unroll
            for (int q = 0; q < 4; q++) acc[mi][ni][q] = 0.f;

    // prefetch registers
    float4 fa[4];      // MODE 1 A (fp32 gather)
    uint4  ha[2];      // MODE 2/3 A (already half)
    uint4  hb0, hb1;   // B (half), named scalars to keep register-resident

    auto load_a = [&](int kt) {
        const int kb = kt * BK;
        if (MODE == 1) {
            if (a_valid && (kb + a_k + 15) < DD) {
                const float* p = X + (size_t)tok * DD + kb + a_k;
                fa[0] = *(const float4*)(p);
                fa[1] = *(const float4*)(p + 4);
                fa[2] = *(const float4*)(p + 8);
                fa[3] = *(const float4*)(p + 12);
            } else {
                float tv[16];
                #pragma unroll
                for (int l = 0; l < 16; l++) {
                    const int k = kb + a_k + l;
                    float v = 0.f;
                    if (a_valid) {
                        if (k < DD)       v = X[(size_t)tok * DD + k];
                        else if (k == DD) v = T[tok];
                    }
                    tv[l] = v;
                }
                fa[0] = make_float4(tv[0], tv[1], tv[2], tv[3]);
                fa[1] = make_float4(tv[4], tv[5], tv[6], tv[7]);
                fa[2] = make_float4(tv[8], tv[9], tv[10], tv[11]);
                fa[3] = make_float4(tv[12], tv[13], tv[14], tv[15]);
            }
        } else {
            if (a_valid) {
                ha[0] = *(const uint4*)(Arow + kb + a_k);
                ha[1] = *(const uint4*)(Arow + kb + a_k + 8);
            } else {
                ha[0] = make_uint4(0, 0, 0, 0);
                ha[1] = make_uint4(0, 0, 0, 0);
            }
        }
    };

    auto store_a = [&](int buf) {
        __half* dst = &As[buf][a_m * RS + a_k];
        if (MODE == 1) {
            __half2 h[8];
            h[0] = __floats2half2_rn(fa[0].x, fa[0].y);
            h[1] = __floats2half2_rn(fa[0].z, fa[0].w);
            h[2] = __floats2half2_rn(fa[1].x, fa[1].y);
            h[3] = __floats2half2_rn(fa[1].z, fa[1].w);
            h[4] = __floats2half2_rn(fa[2].x, fa[2].y);
            h[5] = __floats2half2_rn(fa[2].z, fa[2].w);
            h[6] = __floats2half2_rn(fa[3].x, fa[3].y);
            h[7] = __floats2half2_rn(fa[3].z, fa[3].w);
            *(uint4*)(dst)     = *(uint4*)&h[0];
            *(uint4*)(dst + 8) = *(uint4*)&h[4];
        } else {
            *(uint4*)(dst)     = ha[0];
            *(uint4*)(dst + 8) = ha[1];
        }
    };

    auto load_b = [&](int kt) {
        const int k = kt * BK + b_kk;
        if ((KK % BK == 0) || (k < KK)) {
            const __half* p = Wp + (size_t)k * NN + col0 + b_n0;
            hb0 = *(const uint4*)(p);
            hb1 = *(const uint4*)(p + 8);
        } else {
            hb0 = make_uint4(0, 0, 0, 0);
            hb1 = make_uint4(0, 0, 0, 0);
        }
    };

    auto store_b = [&](int buf) {
        __half* Bb = &Bs[buf][b_n0 * RS + b_kk];
        // 16 halves from 8 named uint32s; all constant-indexed register ops.
        Bb[0 * RS]  = h_lo(hb0.x);  Bb[1 * RS]  = h_hi(hb0.x);
        Bb[2 * RS]  = h_lo(hb0.y);  Bb[3 * RS]  = h_hi(hb0.y);
        Bb[4 * RS]  = h_lo(hb0.z);  Bb[5 * RS]  = h_hi(hb0.z);
        Bb[6 * RS]  = h_lo(hb0.w);  Bb[7 * RS]  = h_hi(hb0.w);
        Bb[8 * RS]  = h_lo(hb1.x);  Bb[9 * RS]  = h_hi(hb1.x);
        Bb[10 * RS] = h_lo(hb1.y);  Bb[11 * RS] = h_hi(hb1.y);
        Bb[12 * RS] = h_lo(hb1.z);  Bb[13 * RS] = h_hi(hb1.z);
        Bb[14 * RS] = h_lo(hb1.w);  Bb[15 * RS] = h_hi(hb1.w);
    };

    auto compute = [&](int buf) {
        const __half* Ab = As[buf];
        const __half* Bb = Bs[buf];
        #pragma unroll
        for (int kk = 0; kk < BK; kk += 16) {
            unsigned af[4][4], bf[4][2];
            #pragma unroll
            for (int mi = 0; mi < 4; mi++) {
                const int base = (wm * 64 + mi * 16 + r) * RS + kk + 2 * c;
                af[mi][0] = *(const unsigned*)(Ab + base);
                af[mi][1] = *(const unsigned*)(Ab + base + 8 * RS);
                af[mi][2] = *(const unsigned*)(Ab + base + 8);
                af[mi][3] = *(const unsigned*)(Ab + base + 8 * RS + 8);
            }
            #pragma unroll
            for (int ni = 0; ni < 4; ni++) {
                const int base = (wn * 32 + ni * 8 + r) * RS + kk + 2 * c;
                bf[ni][0] = *(const unsigned*)(Bb + base);
                bf[ni][1] = *(const unsigned*)(Bb + base + 8);
            }
            #pragma unroll
            for (int mi = 0; mi < 4; mi++)
                #pragma unroll
                for (int ni = 0; ni < 4; ni++)
                    mma_f16(acc[mi][ni], af[mi], bf[ni]);
        }
    };

    // ---- double-buffered mainloop (R4 exact) ----
    load_a(0); load_b(0);
    store_a(0); store_b(0);
    __syncthreads();

    for (int kt = 0; kt < NKT; kt++) {
        const int cur = kt & 1;
        if (kt + 1 < NKT) { load_a(kt + 1); load_b(kt + 1); }
        compute(cur);
        if (kt + 1 < NKT) { store_a(cur ^ 1); store_b(cur ^ 1); }
        __syncthreads();
    }

    // ---- epilogue (R4 exact) ----
    float bias2[4][2];
    #pragma unroll
    for (int ni = 0; ni < 4; ni++) {
        const int col = col0 + wn * 32 + ni * 8 + c * 2;
        bias2[ni][0] = Bp[col];
        bias2[ni][1] = Bp[col + 1];
    }

    #pragma unroll
    for (int mi = 0; mi < 4; mi++) {
        #pragma unroll
        for (int h = 0; h < 2; h++) {
            const int rloc = row0 + wm * 64 + mi * 16 + r + h * 8;
            if (rloc >= m_count) continue;
            const size_t a_idx = (size_t)(m_base + rloc);
            if (MODE == 3) {
                float* dst = g_eout + a_idx * DD;
                const float scale = g_wgt[a_idx];
                #pragma unroll
                for (int ni = 0; ni < 4; ni++) {
                    const int col = col0 + wn * 32 + ni * 8 + c * 2;
                    const float v0 = (acc[mi][ni][h * 2 + 0] + bias2[ni][0]) * scale;
                    const float v1 = (acc[mi][ni][h * 2 + 1] + bias2[ni][1]) * scale;
                    *(float2*)(dst + col) = make_float2(v0, v1);
                }
            } else {
                __half* dst = ((MODE == 1) ? g_h1 : g_h2) + a_idx * HH;
                #pragma unroll
                for (int ni = 0; ni < 4; ni++) {
                    const int col = col0 + wn * 32 + ni * 8 + c * 2;
                    const float v0 = silu_precise(acc[mi][ni][h * 2 + 0] + bias2[ni][0]);
                    const float v1 = silu_precise(acc[mi][ni][h * 2 + 1] + bias2[ni][1]);
                    *(__half2*)(dst + col) = __floats2half2_rn(v0, v1);
                }
            }
        }
    }
}

// ---------------- router logits + top-2 softmax ------------------------------
__global__ __launch_bounds__(256)
void logits_topk_kernel(const float* __restrict__ Rw2, const float* __restrict__ Rb2)
{
    const int warp = (blockIdx.x * (blockDim.x >> 5)) + (threadIdx.x >> 5);
    if (warp >= BB) return;
    const int b = warp;
    const int lane = threadIdx.x & 31;

    float l[EE];
    #pragma unroll
    for (int e = 0; e < EE; e++) l[e] = 0.f;

    const float* __restrict__ hrow = g_h + (size_t)b * HH;
    for (int k = lane; k < HH; k += 32) {
        const float hv = hrow[k];
        const float4 w0 = *(const float4*)(Rw2 + (size_t)k * EE);
        const float4 w1 = *(const float4*)(Rw2 + (size_t)k * EE + 4);
        l[0] = fmaf(hv, w0.x, l[0]);
        l[1] = fmaf(hv, w0.y, l[1]);
        l[2] = fmaf(hv, w0.z, l[2]);
        l[3] = fmaf(hv, w0.w, l[3]);
        l[4] = fmaf(hv, w1.x, l[4]);
        l[5] = fmaf(hv, w1.y, l[5]);
        l[6] = fmaf(hv, w1.z, l[6]);
        l[7] = fmaf(hv, w1.w, l[7]);
    }
    #pragma unroll
    for (int off = 16; off > 0; off >>= 1)
        #pragma unroll
        for (int e = 0; e < EE; e++)
            l[e] += __shfl_xor_sync(0xffffffff, l[e], off);

    if (lane == 0) {
        #pragma unroll
        for (int e = 0; e < EE; e++) l[e] += Rb2[e];
        int i0 = 0;
        #pragma unroll
        for (int e = 1; e < EE; e++) if (l[e] > l[i0]) i0 = e;
        int i1 = (i0 == 0) ? 1 : 0;
        #pragma unroll
        for (int e = 0; e < EE; e++)
            if (e != i0 && l[e] > l[i1]) i1 = e;
        const float e1 = expf(l[i1] - l[i0]);
        const float inv = 1.f / (1.f + e1);
        g_topk_idx[b * 2 + 0] = i0;
        g_topk_idx[b * 2 + 1] = i1;
        g_topk_a[b * 2 + 0] = inv;
        g_topk_a[b * 2 + 1] = e1 * inv;
        atomicAdd(&g_cnt[i0], 1);
        atomicAdd(&g_cnt[i1], 1);
    }
}

// ---------------- bucket offsets ---------------------------------------------
__global__ void scan_kernel()
{
    if (threadIdx.x == 0) {
        int s = 0;
        for (int e = 0; e < EE; e++) {
            g_off[e] = s;
            g_cursor[e] = s;
            s += g_cnt[e];
        }
    }
}

// ---------------- scatter tokens into expert buckets -------------------------
__global__ __launch_bounds__(256)
void scatter_kernel()
{
    const int b = blockIdx.x * blockDim.x + threadIdx.x;
    if (b >= BB) return;
    #pragma unroll
    for (int j = 0; j < TOPK; j++) {
        const int e = g_topk_idx[b * 2 + j];
        const int pos = atomicAdd(&g_cursor[e], 1);
        g_perm[pos] = b;
        g_wgt[pos]  = g_topk_a[b * 2 + j];
        g_slot[b * 2 + j] = pos;
    }
}

// ---------------- deterministic 2-way combine --------------------------------
__global__ __launch_bounds__(256)
void combine_kernel(float* __restrict__ out)
{
    const int idx = blockIdx.x * blockDim.x + threadIdx.x;
    if (idx >= BB * DD / 4) return;
    const int b = idx / (DD / 4);
    const int q = idx % (DD / 4);
    const int s0 = g_slot[b * 2 + 0];
    const int s1 = g_slot[b * 2 + 1];
    const float4 v0 = *((const float4*)g_eout + (size_t)s0 * (DD / 4) + q);
    const float4 v1 = *((const float4*)g_eout + (size_t)s1 * (DD / 4) + q);
    ((float4*)out)[idx] = make_float4(v0.x + v1.x, v0.y + v1.y, v0.z + v1.z, v0.w + v1.w);
}

// ---------------- launch -----------------------------------------------------
extern "C" void kernel_launch(void* const* d_in, const int* in_sizes, int n_in,
                              void* d_out, int out_size)
{
    const float* t   = (const float*)d_in[0];
    const float* x   = (const float*)d_in[1];
    const float* Rw1 = (const float*)d_in[2];
    const float* Rb1 = (const float*)d_in[3];
    const float* Rw2 = (const float*)d_in[4];
    const float* Rb2 = (const float*)d_in[5];
    const float* Ew1 = (const float*)d_in[6];
    const float* Eb1 = (const float*)d_in[7];
    const float* Ew2 = (const float*)d_in[8];
    const float* Eb2 = (const float*)d_in[9];
    const float* Ew3 = (const float*)d_in[10];
    const float* Eb3 = (const float*)d_in[11];
    float* out = (float*)d_out;

    reset_kernel<<<1, 32>>>();

    // pre-pass: elementwise weight casts (identity indexing, trivially correct)
    {
        const int n1 = EE * KXT * HH / 4;
        const int n2 = EE * HH * HH / 4;
        const int n3 = EE * HH * DD / 4;
        cast_w_kernel<<<(n1 + 255) / 256, 256>>>(Ew1, g_w1k, n1);
        cast_w_kernel<<<(n2 + 255) / 256, 256>>>(Ew2, g_w2k, n2);
        cast_w_kernel<<<(n3 + 255) / 256, 256>>>(Ew3, g_w3k, n3);
    }

    // router hidden: exact fp32 (gating selection must match reference)
    router_gemm_kernel<<<dim3(HH / 128, BB / 128, 1), 256>>>(x, t, Rw1, Rb1);

    // logits + top-2 softmax gate (exact fp32)
    logits_topk_kernel<<<BB / 8, 256>>>(Rw2, Rb2);
    scan_kernel<<<1, 32>>>();
    scatter_kernel<<<BB / 256, 256>>>();

    // grouped expert MLP on tensor cores (FP16 mma, fp32 accum)
    hgemm_kernel<1><<<dim3(HH / 128, 256, EE), 256>>>(x, t, g_w1k, Eb1);
    hgemm_kernel<2><<<dim3(HH / 128, 256, EE), 256>>>(nullptr, nullptr, g_w2k, Eb2);
    hgemm_kernel<3><<<dim3(DD / 128, 256, EE), 256>>>(nullptr, nullptr, g_w3k, Eb3);

    // out[b] = alpha0*eout[slot0] + alpha1*eout[slot1]
    combine_kernel<<<(BB * DD / 4 + 255) / 256, 256>>>(out);
}

// round 14
// speedup vs baseline: 3.8648x; 3.8648x over previous
#include <cuda_runtime.h>
#include <cuda_fp16.h>
#include <cstdint>

#define BB 16384
#define DD 256
#define HH 1024
#define EE 8
#define KXT 257   // D+1
#define TOPK 2

// ---------------- scratch (static device memory; no allocations) -------------
__device__ float  g_h[(size_t)BB * HH];          // router hidden (fp32, exact)
__device__ __half g_w1k[(size_t)EE * KXT * HH];  // fc1 W half, K-major
__device__ __half g_w2k[(size_t)EE * HH * HH];   // fc2 W half, K-major
__device__ __half g_w3k[(size_t)EE * HH * DD];   // fc3 W half, K-major
__device__ __half g_h1[(size_t)2 * BB * HH];     // expert fc1 out (half)
__device__ __half g_h2[(size_t)2 * BB * HH];     // expert fc2 out (half)
__device__ float  g_eout[(size_t)2 * BB * DD];   // scaled expert out (fp32)
__device__ int    g_perm[2 * BB];
__device__ float  g_wgt[2 * BB];
__device__ int    g_slot[2 * BB];
__device__ int    g_topk_idx[BB * TOPK];
__device__ float  g_topk_a[BB * TOPK];
__device__ int    g_cnt[EE];
__device__ int    g_off[EE];
__device__ int    g_cursor[EE];

__device__ __forceinline__ float silu_precise(float v) {
    return v / (1.f + expf(-v));
}

__device__ __forceinline__ __half h_lo(uint32_t w) {
    return __ushort_as_half((unsigned short)(w & 0xFFFFu));
}
__device__ __forceinline__ __half h_hi(uint32_t w) {
    return __ushort_as_half((unsigned short)(w >> 16));
}

__device__ __forceinline__ void mma_f16(float* d, const unsigned* a, const unsigned* b) {
    asm volatile(
        "mma.sync.aligned.m16n8k16.row.col.f32.f16.f16.f32 "
        "{%0,%1,%2,%3}, {%4,%5,%6,%7}, {%8,%9}, {%0,%1,%2,%3};"
        : "+f"(d[0]), "+f"(d[1]), "+f"(d[2]), "+f"(d[3])
        : "r"(a[0]), "r"(a[1]), "r"(a[2]), "r"(a[3]), "r"(b[0]), "r"(b[1]));
}

// ---------------- reset ------------------------------------------------------
__global__ void reset_kernel() {
    if (threadIdx.x < EE) g_cnt[threadIdx.x] = 0;
}

// ---------------- pre-pass: ELEMENTWISE fp32->fp16 weight cast ---------------
// Destination resolved IN DEVICE CODE (never pass __device__ symbols from host:
// the host shadow address routes all traffic over ATS/C2C — the R12/13 3.2x bug).
template <int WS>
__global__ __launch_bounds__(256)
void cast_w_kernel(const float* __restrict__ W, int n4)
{
    __half* __restrict__ Wh = (WS == 1) ? g_w1k : (WS == 2) ? g_w2k : g_w3k;
    const int i = blockIdx.x * 256 + threadIdx.x;
    if (i >= n4) return;
    const float4 v = ((const float4*)W)[i];
    ((__half2*)Wh)[i * 2]     = __floats2half2_rn(v.x, v.y);
    ((__half2*)Wh)[i * 2 + 1] = __floats2half2_rn(v.z, v.w);
}

// ---------------- fp32 router GEMM (exact; gating must match reference) ------
__global__ __launch_bounds__(256)
void router_gemm_kernel(const float* __restrict__ X, const float* __restrict__ T,
                        const float* __restrict__ W, const float* __restrict__ Bias)
{
    constexpr int KK = KXT, NN = HH;
    constexpr int BM = 128, BN = 128, BK = 8;
    constexpr int NKT = (KK + BK - 1) / BK;

    const int row0 = blockIdx.y * BM;
    const int col0 = blockIdx.x * BN;

    __shared__ __align__(16) float As[BK][BM + 4];
    __shared__ __align__(16) float Bs[BK][BN + 4];

    const int tid = threadIdx.x;
    const int tx = tid & 15;
    const int ty = tid >> 4;
    const int a_row = tid >> 1;
    const int a_k4  = (tid & 1) * 4;
    const int b_k  = tid >> 5;
    const int b_n  = (tid & 31) * 4;

    const int tok = row0 + a_row;

    float acc[8][8];
    #pragma unroll
    for (int i = 0; i < 8; i++)
        #pragma unroll
        for (int j = 0; j < 8; j++) acc[i][j] = 0.f;

    for (int kt = 0; kt < NKT; kt++) {
        const int kb = kt * BK;
        #pragma unroll
        for (int l = 0; l < 4; l++) {
            const int k = kb + a_k4 + l;
            float v = 0.f;
            if (k < DD)       v = X[(size_t)tok * DD + k];
            else if (k == DD) v = T[tok];
            As[a_k4 + l][a_row] = v;
        }
        {
            const int k = kb + b_k;
            float4 v = make_float4(0.f, 0.f, 0.f, 0.f);
            if (k < KK) v = *(const float4*)(W + (size_t)k * NN + col0 + b_n);
            Bs[b_k][b_n + 0] = v.x;
            Bs[b_k][b_n + 1] = v.y;
            Bs[b_k][b_n + 2] = v.z;
            Bs[b_k][b_n + 3] = v.w;
        }
        __syncthreads();
        #pragma unroll
        for (int k = 0; k < BK; k++) {
            float a[8], b[8];
            *(float4*)(a)     = *(const float4*)&As[k][ty * 8];
            *(float4*)(a + 4) = *(const float4*)&As[k][ty * 8 + 4];
            *(float4*)(b)     = *(const float4*)&Bs[k][tx * 8];
            *(float4*)(b + 4) = *(const float4*)&Bs[k][tx * 8 + 4];
            #pragma unroll
            for (int i = 0; i < 8; i++)
                #pragma unroll
                for (int j = 0; j < 8; j++)
                    acc[i][j] = fmaf(a[i], b[j], acc[i][j]);
        }
        __syncthreads();
    }

    float bias[8];
    #pragma unroll
    for (int j = 0; j < 8; j++) bias[j] = Bias[col0 + tx * 8 + j];

    #pragma unroll
    for (int i = 0; i < 8; i++) {
        const int rloc = row0 + ty * 8 + i;
        float* dst = g_h + (size_t)rloc * HH;
        float tmp[8];
        #pragma unroll
        for (int j = 0; j < 8; j++)
            tmp[j] = silu_precise(acc[i][j] + bias[j]);
        *(float4*)(dst + col0 + tx * 8)     = make_float4(tmp[0], tmp[1], tmp[2], tmp[3]);
        *(float4*)(dst + col0 + tx * 8 + 4) = make_float4(tmp[4], tmp[5], tmp[6], tmp[7]);
    }
}

// ---------------- FP16 tensor-core grouped GEMM (R4 structure, half-B feed) --
// Weight base pointer resolved IN DEVICE CODE from the __device__ globals.
// MODE 1: fc1 : A = [x|t] gathered by g_perm (K=257),  W=g_w1k, silu  -> g_h1
// MODE 2: fc2 : A = g_h1 (K=1024),                     W=g_w2k, silu  -> g_h2
// MODE 3: fc3 : A = g_h2 (K=1024),                     W=g_w3k, *alpha-> g_eout
template <int MODE>
__global__ __launch_bounds__(256)
void hgemm_kernel(const float* __restrict__ X, const float* __restrict__ T,
                  const float* __restrict__ Bias)
{
    constexpr int KK = (MODE == 1) ? KXT : HH;
    constexpr int NN = (MODE == 3) ? DD : HH;
    constexpr int BM = 128, BN = 128, BK = 32;
    constexpr int RS = BK + 8;                 // 40 halves
    constexpr int NKT = (KK + BK - 1) / BK;

    const int e = blockIdx.z;
    const int m_base  = g_off[e];
    const int m_count = g_cnt[e];
    const int row0 = blockIdx.y * BM;
    if (row0 >= m_count) return;
    const int col0 = blockIdx.x * BN;

    const __half* __restrict__ Wg =
        (MODE == 1) ? g_w1k : (MODE == 2) ? g_w2k : g_w3k;
    const __half* __restrict__ Wp = Wg + (size_t)e * KK * NN;
    const float* __restrict__ Bp = Bias + (size_t)e * NN;

    __shared__ __align__(16) __half As[2][BM * RS];
    __shared__ __align__(16) __half Bs[2][BN * RS];

    const int tid  = threadIdx.x;
    const int warp = tid >> 5;
    const int lane = tid & 31;
    const int wm = warp >> 2;       // 0..1 : 64-row slab
    const int wn = warp & 3;        // 0..3 : 32-col slab
    const int r  = lane >> 2;       // 0..7
    const int c  = lane & 3;        // 0..3

    // A loader: thread -> (row a_m, 16 consecutive k halves)
    const int a_m = tid >> 1;              // 0..127
    const int a_k = (tid & 1) * 16;        // 0 or 16
    const bool a_valid = (row0 + a_m) < m_count;
    int tok = 0;
    const __half* __restrict__ Arow = nullptr;
    if (MODE == 1) {
        if (a_valid) tok = g_perm[m_base + row0 + a_m];
    } else {
        const __half* src = (MODE == 2) ? g_h1 : g_h2;
        Arow = src + (size_t)(m_base + row0 + a_m) * KK;
    }

    // B loader: thread -> (k = b_kk, 16 consecutive n)
    const int b_kk = tid >> 3;             // 0..31
    const int b_n0 = (tid & 7) * 16;       // 0..112

    float acc[4][4][4];
    #pragma unroll
    for (int mi = 0; mi < 4; mi++)
        #pragma unroll
        for (int ni = 0; ni < 4; ni++)
            #pragma unroll
            for (int q = 0; q < 4; q++) acc[mi][ni][q] = 0.f;

    // prefetch registers
    float4 fa[4];      // MODE 1 A (fp32 gather)
    uint4  ha[2];      // MODE 2/3 A (already half)
    uint4  hb0, hb1;   // B (half)

    auto load_a = [&](int kt) {
        const int kb = kt * BK;
        if (MODE == 1) {
            if (a_valid && (kb + a_k + 15) < DD) {
                const float* p = X + (size_t)tok * DD + kb + a_k;
                fa[0] = *(const float4*)(p);
                fa[1] = *(const float4*)(p + 4);
                fa[2] = *(const float4*)(p + 8);
                fa[3] = *(const float4*)(p + 12);
            } else {
                float tv[16];
                #pragma unroll
                for (int l = 0; l < 16; l++) {
                    const int k = kb + a_k + l;
                    float v = 0.f;
                    if (a_valid) {
                        if (k < DD)       v = X[(size_t)tok * DD + k];
                        else if (k == DD) v = T[tok];
                    }
                    tv[l] = v;
                }
                fa[0] = make_float4(tv[0], tv[1], tv[2], tv[3]);
                fa[1] = make_float4(tv[4], tv[5], tv[6], tv[7]);
                fa[2] = make_float4(tv[8], tv[9], tv[10], tv[11]);
                fa[3] = make_float4(tv[12], tv[13], tv[14], tv[15]);
            }
        } else {
            if (a_valid) {
                ha[0] = *(const uint4*)(Arow + kb + a_k);
                ha[1] = *(const uint4*)(Arow + kb + a_k + 8);
            } else {
                ha[0] = make_uint4(0, 0, 0, 0);
                ha[1] = make_uint4(0, 0, 0, 0);
            }
        }
    };

    auto store_a = [&](int buf) {
        __half* dst = &As[buf][a_m * RS + a_k];
        if (MODE == 1) {
            __half2 h[8];
            h[0] = __floats2half2_rn(fa[0].x, fa[0].y);
            h[1] = __floats2half2_rn(fa[0].z, fa[0].w);
            h[2] = __floats2half2_rn(fa[1].x, fa[1].y);
            h[3] = __floats2half2_rn(fa[1].z, fa[1].w);
            h[4] = __floats2half2_rn(fa[2].x, fa[2].y);
            h[5] = __floats2half2_rn(fa[2].z, fa[2].w);
            h[6] = __floats2half2_rn(fa[3].x, fa[3].y);
            h[7] = __floats2half2_rn(fa[3].z, fa[3].w);
            *(uint4*)(dst)     = *(uint4*)&h[0];
            *(uint4*)(dst + 8) = *(uint4*)&h[4];
        } else {
            *(uint4*)(dst)     = ha[0];
            *(uint4*)(dst + 8) = ha[1];
        }
    };

    auto load_b = [&](int kt) {
        const int k = kt * BK + b_kk;
        if ((KK % BK == 0) || (k < KK)) {
            const __half* p = Wp + (size_t)k * NN + col0 + b_n0;
            hb0 = *(const uint4*)(p);
            hb1 = *(const uint4*)(p + 8);
        } else {
            hb0 = make_uint4(0, 0, 0, 0);
            hb1 = make_uint4(0, 0, 0, 0);
        }
    };

    auto store_b = [&](int buf) {
        __half* Bb = &Bs[buf][b_n0 * RS + b_kk];
        Bb[0 * RS]  = h_lo(hb0.x);  Bb[1 * RS]  = h_hi(hb0.x);
        Bb[2 * RS]  = h_lo(hb0.y);  Bb[3 * RS]  = h_hi(hb0.y);
        Bb[4 * RS]  = h_lo(hb0.z);  Bb[5 * RS]  = h_hi(hb0.z);
        Bb[6 * RS]  = h_lo(hb0.w);  Bb[7 * RS]  = h_hi(hb0.w);
        Bb[8 * RS]  = h_lo(hb1.x);  Bb[9 * RS]  = h_hi(hb1.x);
        Bb[10 * RS] = h_lo(hb1.y);  Bb[11 * RS] = h_hi(hb1.y);
        Bb[12 * RS] = h_lo(hb1.z);  Bb[13 * RS] = h_hi(hb1.z);
        Bb[14 * RS] = h_lo(hb1.w);  Bb[15 * RS] = h_hi(hb1.w);
    };

    auto compute = [&](int buf) {
        const __half* Ab = As[buf];
        const __half* Bb = Bs[buf];
        #pragma unroll
        for (int kk = 0; kk < BK; kk += 16) {
            unsigned af[4][4], bf[4][2];
            #pragma unroll
            for (int mi = 0; mi < 4; mi++) {
                const int base = (wm * 64 + mi * 16 + r) * RS + kk + 2 * c;
                af[mi][0] = *(const unsigned*)(Ab + base);
                af[mi][1] = *(const unsigned*)(Ab + base + 8 * RS);
                af[mi][2] = *(const unsigned*)(Ab + base + 8);
                af[mi][3] = *(const unsigned*)(Ab + base + 8 * RS + 8);
            }
            #pragma unroll
            for (int ni = 0; ni < 4; ni++) {
                const int base = (wn * 32 + ni * 8 + r) * RS + kk + 2 * c;
                bf[ni][0] = *(const unsigned*)(Bb + base);
                bf[ni][1] = *(const unsigned*)(Bb + base + 8);
            }
            #pragma unroll
            for (int mi = 0; mi < 4; mi++)
                #pragma unroll
                for (int ni = 0; ni < 4; ni++)
                    mma_f16(acc[mi][ni], af[mi], bf[ni]);
        }
    };

    // ---- double-buffered mainloop (R4 exact) ----
    load_a(0); load_b(0);
    store_a(0); store_b(0);
    __syncthreads();

    for (int kt = 0; kt < NKT; kt++) {
        const int cur = kt & 1;
        if (kt + 1 < NKT) { load_a(kt + 1); load_b(kt + 1); }
        compute(cur);
        if (kt + 1 < NKT) { store_a(cur ^ 1); store_b(cur ^ 1); }
        __syncthreads();
    }

    // ---- epilogue (R4 exact) ----
    float bias2[4][2];
    #pragma unroll
    for (int ni = 0; ni < 4; ni++) {
        const int col = col0 + wn * 32 + ni * 8 + c * 2;
        bias2[ni][0] = Bp[col];
        bias2[ni][1] = Bp[col + 1];
    }

    #pragma unroll
    for (int mi = 0; mi < 4; mi++) {
        #pragma unroll
        for (int h = 0; h < 2; h++) {
            const int rloc = row0 + wm * 64 + mi * 16 + r + h * 8;
            if (rloc >= m_count) continue;
            const size_t a_idx = (size_t)(m_base + rloc);
            if (MODE == 3) {
                float* dst = g_eout + a_idx * DD;
                const float scale = g_wgt[a_idx];
                #pragma unroll
                for (int ni = 0; ni < 4; ni++) {
                    const int col = col0 + wn * 32 + ni * 8 + c * 2;
                    const float v0 = (acc[mi][ni][h * 2 + 0] + bias2[ni][0]) * scale;
                    const float v1 = (acc[mi][ni][h * 2 + 1] + bias2[ni][1]) * scale;
                    *(float2*)(dst + col) = make_float2(v0, v1);
                }
            } else {
                __half* dst = ((MODE == 1) ? g_h1 : g_h2) + a_idx * HH;
                #pragma unroll
                for (int ni = 0; ni < 4; ni++) {
                    const int col = col0 + wn * 32 + ni * 8 + c * 2;
                    const float v0 = silu_precise(acc[mi][ni][h * 2 + 0] + bias2[ni][0]);
                    const float v1 = silu_precise(acc[mi][ni][h * 2 + 1] + bias2[ni][1]);
                    *(__half2*)(dst + col) = __floats2half2_rn(v0, v1);
                }
            }
        }
    }
}

// ---------------- router logits + top-2 softmax ------------------------------
__global__ __launch_bounds__(256)
void logits_topk_kernel(const float* __restrict__ Rw2, const float* __restrict__ Rb2)
{
    const int warp = (blockIdx.x * (blockDim.x >> 5)) + (threadIdx.x >> 5);
    if (warp >= BB) return;
    const int b = warp;
    const int lane = threadIdx.x & 31;

    float l[EE];
    #pragma unroll
    for (int e = 0; e < EE; e++) l[e] = 0.f;

    const float* __restrict__ hrow = g_h + (size_t)b * HH;
    for (int k = lane; k < HH; k += 32) {
        const float hv = hrow[k];
        const float4 w0 = *(const float4*)(Rw2 + (size_t)k * EE);
        const float4 w1 = *(const float4*)(Rw2 + (size_t)k * EE + 4);
        l[0] = fmaf(hv, w0.x, l[0]);
        l[1] = fmaf(hv, w0.y, l[1]);
        l[2] = fmaf(hv, w0.z, l[2]);
        l[3] = fmaf(hv, w0.w, l[3]);
        l[4] = fmaf(hv, w1.x, l[4]);
        l[5] = fmaf(hv, w1.y, l[5]);
        l[6] = fmaf(hv, w1.z, l[6]);
        l[7] = fmaf(hv, w1.w, l[7]);
    }
    #pragma unroll
    for (int off = 16; off > 0; off >>= 1)
        #pragma unroll
        for (int e = 0; e < EE; e++)
            l[e] += __shfl_xor_sync(0xffffffff, l[e], off);

    if (lane == 0) {
        #pragma unroll
        for (int e = 0; e < EE; e++) l[e] += Rb2[e];
        int i0 = 0;
        #pragma unroll
        for (int e = 1; e < EE; e++) if (l[e] > l[i0]) i0 = e;
        int i1 = (i0 == 0) ? 1 : 0;
        #pragma unroll
        for (int e = 0; e < EE; e++)
            if (e != i0 && l[e] > l[i1]) i1 = e;
        const float e1 = expf(l[i1] - l[i0]);
        const float inv = 1.f / (1.f + e1);
        g_topk_idx[b * 2 + 0] = i0;
        g_topk_idx[b * 2 + 1] = i1;
        g_topk_a[b * 2 + 0] = inv;
        g_topk_a[b * 2 + 1] = e1 * inv;
        atomicAdd(&g_cnt[i0], 1);
        atomicAdd(&g_cnt[i1], 1);
    }
}

// ---------------- bucket offsets ---------------------------------------------
__global__ void scan_kernel()
{
    if (threadIdx.x == 0) {
        int s = 0;
        for (int e = 0; e < EE; e++) {
            g_off[e] = s;
            g_cursor[e] = s;
            s += g_cnt[e];
        }
    }
}

// ---------------- scatter tokens into expert buckets -------------------------
__global__ __launch_bounds__(256)
void scatter_kernel()
{
    const int b = blockIdx.x * blockDim.x + threadIdx.x;
    if (b >= BB) return;
    #pragma unroll
    for (int j = 0; j < TOPK; j++) {
        const int e = g_topk_idx[b * 2 + j];
        const int pos = atomicAdd(&g_cursor[e], 1);
        g_perm[pos] = b;
        g_wgt[pos]  = g_topk_a[b * 2 + j];
        g_slot[b * 2 + j] = pos;
    }
}

// ---------------- deterministic 2-way combine --------------------------------
__global__ __launch_bounds__(256)
void combine_kernel(float* __restrict__ out)
{
    const int idx = blockIdx.x * blockDim.x + threadIdx.x;
    if (idx >= BB * DD / 4) return;
    const int b = idx / (DD / 4);
    const int q = idx % (DD / 4);
    const int s0 = g_slot[b * 2 + 0];
    const int s1 = g_slot[b * 2 + 1];
    const float4 v0 = *((const float4*)g_eout + (size_t)s0 * (DD / 4) + q);
    const float4 v1 = *((const float4*)g_eout + (size_t)s1 * (DD / 4) + q);
    ((float4*)out)[idx] = make_float4(v0.x + v1.x, v0.y + v1.y, v0.z + v1.z, v0.w + v1.w);
}

// ---------------- launch -----------------------------------------------------
extern "C" void kernel_launch(void* const* d_in, const int* in_sizes, int n_in,
                              void* d_out, int out_size)
{
    const float* t   = (const float*)d_in[0];
    const float* x   = (const float*)d_in[1];
    const float* Rw1 = (const float*)d_in[2];
    const float* Rb1 = (const float*)d_in[3];
    const float* Rw2 = (const float*)d_in[4];
    const float* Rb2 = (const float*)d_in[5];
    const float* Ew1 = (const float*)d_in[6];
    const float* Eb1 = (const float*)d_in[7];
    const float* Ew2 = (const float*)d_in[8];
    const float* Eb2 = (const float*)d_in[9];
    const float* Ew3 = (const float*)d_in[10];
    const float* Eb3 = (const float*)d_in[11];
    float* out = (float*)d_out;

    reset_kernel<<<1, 32>>>();

    // pre-pass: elementwise weight casts; destinations resolved device-side
    {
        const int n1 = EE * KXT * HH / 4;
        const int n2 = EE * HH * HH / 4;
        const int n3 = EE * HH * DD / 4;
        cast_w_kernel<1><<<(n1 + 255) / 256, 256>>>(Ew1, n1);
        cast_w_kernel<2><<<(n2 + 255) / 256, 256>>>(Ew2, n2);
        cast_w_kernel<3><<<(n3 + 255) / 256, 256>>>(Ew3, n3);
    }

    // router hidden: exact fp32 (gating selection must match reference)
    router_gemm_kernel<<<dim3(HH / 128, BB / 128, 1), 256>>>(x, t, Rw1, Rb1);

    // logits + top-2 softmax gate (exact fp32)
    logits_topk_kernel<<<BB / 8, 256>>>(Rw2, Rb2);
    scan_kernel<<<1, 32>>>();
    scatter_kernel<<<BB / 256, 256>>>();

    // grouped expert MLP on tensor cores (FP16 mma, fp32 accum)
    hgemm_kernel<1><<<dim3(HH / 128, 256, EE), 256>>>(x, t, Eb1);
    hgemm_kernel<2><<<dim3(HH / 128, 256, EE), 256>>>(nullptr, nullptr, Eb2);
    hgemm_kernel<3><<<dim3(DD / 128, 256, EE), 256>>>(nullptr, nullptr, Eb3);

    // out[b] = alpha0*eout[slot0] + alpha1*eout[slot1]
    combine_kernel<<<(BB * DD / 4 + 255) / 256, 256>>>(out);
}

// round 15
// speedup vs baseline: 4.7492x; 1.2288x over previous
#include <cuda_runtime.h>
#include <cuda_fp16.h>
#include <cstdint>

#define BB 16384
#define DD 256
#define HH 1024
#define EE 8
#define KXT 257   // D+1
#define TOPK 2
#define KP1 320   // K of fc1 padded to 5*64

// ---------------- scratch (static device memory; no allocations) -------------
// RULE: device symbols are ONLY dereferenced from device code (ATS shadow bug).
__device__ float  g_h[(size_t)BB * HH];            // router hidden (fp32, exact)
__device__ __half g_xh[(size_t)BB * KP1];          // packed [x|t] half, K-padded
__device__ __half g_w1t[(size_t)EE * HH * KP1];    // fc1 W: [E][N][Kpad] half (n-major)
__device__ __half g_w2t[(size_t)EE * HH * HH];     // fc2 W: [E][N][K] half
__device__ __half g_w3t[(size_t)EE * DD * HH];     // fc3 W: [E][N][K] half
__device__ __half g_h1[(size_t)2 * BB * HH];       // expert fc1 out (half)
__device__ __half g_h2[(size_t)2 * BB * HH];       // expert fc2 out (half)
__device__ float  g_eout[(size_t)2 * BB * DD];     // scaled expert out (fp32)
__device__ int    g_perm[2 * BB];
__device__ float  g_wgt[2 * BB];
__device__ int    g_slot[2 * BB];
__device__ int    g_topk_idx[BB * TOPK];
__device__ float  g_topk_a[BB * TOPK];
__device__ int    g_cnt[EE];
__device__ int    g_off[EE];
__device__ int    g_cursor[EE];

__device__ __forceinline__ float silu_precise(float v) {
    return v / (1.f + expf(-v));
}

__device__ __forceinline__ uint32_t smem_u32(const void* p) {
    uint32_t a;
    asm("{ .reg .u64 t; cvta.to.shared.u64 t, %1; cvt.u32.u64 %0, t; }"
        : "=r"(a) : "l"(p));
    return a;
}

__device__ __forceinline__ void ldmatrix_x4(uint32_t* r, uint32_t addr) {
    asm volatile("ldmatrix.sync.aligned.m8n8.x4.shared.b16 {%0,%1,%2,%3}, [%4];"
                 : "=r"(r[0]), "=r"(r[1]), "=r"(r[2]), "=r"(r[3]) : "r"(addr));
}

__device__ __forceinline__ void mma_f16(float* d, const uint32_t* a, const uint32_t* b) {
    asm volatile(
        "mma.sync.aligned.m16n8k16.row.col.f32.f16.f16.f32 "
        "{%0,%1,%2,%3}, {%4,%5,%6,%7}, {%8,%9}, {%0,%1,%2,%3};"
        : "+f"(d[0]), "+f"(d[1]), "+f"(d[2]), "+f"(d[3])
        : "r"(a[0]), "r"(a[1]), "r"(a[2]), "r"(a[3]), "r"(b[0]), "r"(b[1]));
}

// ---------------- reset ------------------------------------------------------
__global__ void reset_kernel() {
    if (threadIdx.x < EE) g_cnt[threadIdx.x] = 0;
}

// ---------------- pre-pass: pack [x|t] to half, K-padded ---------------------
__global__ __launch_bounds__(256)
void pack_x_kernel(const float* __restrict__ X, const float* __restrict__ T)
{
    const int i = blockIdx.x * 256 + threadIdx.x;   // half2 index
    if (i >= BB * (KP1 / 2)) return;
    const int b = i / (KP1 / 2);
    const int k = (i % (KP1 / 2)) * 2;
    __half2 h;
    if (k + 1 < DD) {
        const float2 v = *(const float2*)(X + (size_t)b * DD + k);
        h = __floats2half2_rn(v.x, v.y);
    } else if (k == DD) {
        h = __floats2half2_rn(T[b], 0.f);
    } else {
        h = __floats2half2_rn(0.f, 0.f);
    }
    *((__half2*)g_xh + i) = h;
}

// ---------------- pre-pass: transpose-convert weights to half [E][N][KPad] ---
// Destination resolved in device code (WS template), never host-passed.
template <int WS>
__global__ __launch_bounds__(256)
void convert_w_kernel(const float* __restrict__ W, int K, int N, int KPad)
{
    __half* __restrict__ Wh = (WS == 1) ? g_w1t : (WS == 2) ? g_w2t : g_w3t;
    __shared__ float tile[32][33];
    const int e  = blockIdx.z;
    const float* Wp = W + (size_t)e * K * N;
    __half* Whp = Wh + (size_t)e * N * KPad;
    const int n0 = blockIdx.x * 32;
    const int k0 = blockIdx.y * 32;
    const int tx = threadIdx.x, ty = threadIdx.y;
    #pragma unroll
    for (int i = 0; i < 4; i++) {
        const int k = k0 + ty + i * 8;
        const int n = n0 + tx;
        tile[ty + i * 8][tx] = (k < K) ? Wp[(size_t)k * N + n] : 0.f;
    }
    __syncthreads();
    #pragma unroll
    for (int i = 0; i < 4; i++) {
        const int n = n0 + ty + i * 8;
        const int k = k0 + tx;
        if (k < KPad) Whp[(size_t)n * KPad + k] = __float2half_rn(tile[tx][ty + i * 8]);
    }
}

// ---------------- fp32 router GEMM (exact; gating must match reference) ------
__global__ __launch_bounds__(256)
void router_gemm_kernel(const float* __restrict__ X, const float* __restrict__ T,
                        const float* __restrict__ W, const float* __restrict__ Bias)
{
    constexpr int KK = KXT, NN = HH;
    constexpr int BM = 128, BN = 128, BK = 8;
    constexpr int NKT = (KK + BK - 1) / BK;

    const int row0 = blockIdx.y * BM;
    const int col0 = blockIdx.x * BN;

    __shared__ __align__(16) float As[BK][BM + 4];
    __shared__ __align__(16) float Bs[BK][BN + 4];

    const int tid = threadIdx.x;
    const int tx = tid & 15;
    const int ty = tid >> 4;
    const int a_row = tid >> 1;
    const int a_k4  = (tid & 1) * 4;
    const int b_k  = tid >> 5;
    const int b_n  = (tid & 31) * 4;

    const int tok = row0 + a_row;

    float acc[8][8];
    #pragma unroll
    for (int i = 0; i < 8; i++)
        #pragma unroll
        for (int j = 0; j < 8; j++) acc[i][j] = 0.f;

    for (int kt = 0; kt < NKT; kt++) {
        const int kb = kt * BK;
        #pragma unroll
        for (int l = 0; l < 4; l++) {
            const int k = kb + a_k4 + l;
            float v = 0.f;
            if (k < DD)       v = X[(size_t)tok * DD + k];
            else if (k == DD) v = T[tok];
            As[a_k4 + l][a_row] = v;
        }
        {
            const int k = kb + b_k;
            float4 v = make_float4(0.f, 0.f, 0.f, 0.f);
            if (k < KK) v = *(const float4*)(W + (size_t)k * NN + col0 + b_n);
            Bs[b_k][b_n + 0] = v.x;
            Bs[b_k][b_n + 1] = v.y;
            Bs[b_k][b_n + 2] = v.z;
            Bs[b_k][b_n + 3] = v.w;
        }
        __syncthreads();
        #pragma unroll
        for (int k = 0; k < BK; k++) {
            float a[8], b[8];
            *(float4*)(a)     = *(const float4*)&As[k][ty * 8];
            *(float4*)(a + 4) = *(const float4*)&As[k][ty * 8 + 4];
            *(float4*)(b)     = *(const float4*)&Bs[k][tx * 8];
            *(float4*)(b + 4) = *(const float4*)&Bs[k][tx * 8 + 4];
            #pragma unroll
            for (int i = 0; i < 8; i++)
                #pragma unroll
                for (int j = 0; j < 8; j++)
                    acc[i][j] = fmaf(a[i], b[j], acc[i][j]);
        }
        __syncthreads();
    }

    float bias[8];
    #pragma unroll
    for (int j = 0; j < 8; j++) bias[j] = Bias[col0 + tx * 8 + j];

    #pragma unroll
    for (int i = 0; i < 8; i++) {
        const int rloc = row0 + ty * 8 + i;
        float* dst = g_h + (size_t)rloc * HH;
        float tmp[8];
        #pragma unroll
        for (int j = 0; j < 8; j++)
            tmp[j] = silu_precise(acc[i][j] + bias[j]);
        *(float4*)(dst + col0 + tx * 8)     = make_float4(tmp[0], tmp[1], tmp[2], tmp[3]);
        *(float4*)(dst + col0 + tx * 8 + 4) = make_float4(tmp[4], tmp[5], tmp[6], tmp[7]);
    }
}

// ---------------- FP16 mma.sync grouped GEMM (ldmatrix, sync double buffer) --
// All operands pre-converted half; weights n-major [E][N][KPad]; K padded (no
// edges). Loader: 256 threads x 2 rows x 2 k-chunks x 16B = full 128x64h tile.
// MODE 1: fc1 : A = g_xh rows via g_perm (Kpad=320), W=g_w1t, silu  -> g_h1
// MODE 2: fc2 : A = g_h1 (K=1024),                   W=g_w2t, silu  -> g_h2
// MODE 3: fc3 : A = g_h2 (K=1024),                   W=g_w3t, *alpha-> g_eout
#define HG_RS 72                      // 64 + 8 halves (144B row stride)
#define HG_TILE (128 * HG_RS)         // halves per (A or B) buffer tile
#define HG_SMEM_BYTES (2 * HG_TILE * 2 * 2)   // 2 bufs x (A+B) = 73728 B

template <int MODE>
__global__ __launch_bounds__(256)
void hgemm5_kernel(const float* __restrict__ Bias)
{
    constexpr int KPAD = (MODE == 1) ? KP1 : HH;
    constexpr int NN   = (MODE == 3) ? DD : HH;
    constexpr int NKT  = KPAD / 64;

    const int e = blockIdx.z;
    const int m_base  = g_off[e];
    const int m_count = g_cnt[e];
    const int row0 = blockIdx.y * 128;
    if (row0 >= m_count) return;
    const int col0 = blockIdx.x * 128;

    extern __shared__ __half smem[];
    __half* Asm = smem;                     // [2][HG_TILE]
    __half* Bsm = smem + 2 * HG_TILE;       // [2][HG_TILE]

    const int tid  = threadIdx.x;
    const int warp = tid >> 5;
    const int lane = tid & 31;
    const int wm = warp >> 2;       // 0..1 : 64-row slab
    const int wn = warp & 3;        // 0..3 : 32-col slab
    const int r  = lane >> 2;       // 0..7
    const int c  = lane & 3;        // 0..3

    // ---- loader: rows {lrow, lrow+64} x k-chunks {lc16*8, lc16*8+32} --------
    const int lrow = tid >> 2;      // 0..63
    const int lc16 = tid & 3;       // 0..3

    const __half* srcA[2];
    bool validA[2];
    const __half* Wg =
        (MODE == 1) ? g_w1t : (MODE == 2) ? g_w2t : g_w3t;
    const __half* Wbase = Wg + (size_t)e * NN * KPAD + (size_t)col0 * KPAD;
    const __half* srcB[2];

    #pragma unroll
    for (int i = 0; i < 2; i++) {
        const int rowi = lrow + i * 64;
        const int rloc = row0 + rowi;
        const bool valid = rloc < m_count;
        validA[i] = valid;
        const __half* p;
        if (MODE == 1)      p = g_xh + (valid ? (size_t)g_perm[m_base + rloc] * KP1 : 0);
        else if (MODE == 2) p = g_h1 + (valid ? (size_t)(m_base + rloc) * HH : 0);
        else                p = g_h2 + (valid ? (size_t)(m_base + rloc) * HH : 0);
        srcA[i] = p + lc16 * 8;
        srcB[i] = Wbase + (size_t)rowi * KPAD + lc16 * 8;
    }
    const int dstoff[2] = { lrow * HG_RS + lc16 * 8,
                            (lrow + 64) * HG_RS + lc16 * 8 };

    const uint32_t asm_u32 = smem_u32(Asm);
    const uint32_t bsm_u32 = smem_u32(Bsm);

    uint4 ra[2][2], rb[2][2];
    auto load_regs = [&](int kt) {
        const int koff = kt * 64;
        #pragma unroll
        for (int i = 0; i < 2; i++) {
            #pragma unroll
            for (int j = 0; j < 2; j++) {
                ra[i][j] = validA[i] ? *(const uint4*)(srcA[i] + koff + j * 32)
                                     : make_uint4(0, 0, 0, 0);
                rb[i][j] = *(const uint4*)(srcB[i] + koff + j * 32);
            }
        }
    };
    auto store_regs = [&](int buf) {
        __half* Ab = Asm + buf * HG_TILE;
        __half* Bb = Bsm + buf * HG_TILE;
        #pragma unroll
        for (int i = 0; i < 2; i++) {
            #pragma unroll
            for (int j = 0; j < 2; j++) {
                *(uint4*)(Ab + dstoff[i] + j * 32) = ra[i][j];
                *(uint4*)(Bb + dstoff[i] + j * 32) = rb[i][j];
            }
        }
    };

    float acc[4][4][4];
    #pragma unroll
    for (int mi = 0; mi < 4; mi++)
        #pragma unroll
        for (int ni = 0; ni < 4; ni++)
            #pragma unroll
            for (int q = 0; q < 4; q++) acc[mi][ni][q] = 0.f;

    // ldmatrix lane addressing (element offsets within a tile)
    const int a_lrow = wm * 64 + (lane & 15);
    const int a_lcol = (lane >> 4) * 8;
    const int b_lrow = wn * 32 + ((lane >> 4) & 1) * 8 + (lane & 7);
    const int b_lcol = ((lane >> 3) & 1) * 8;

    auto compute_buf = [&](int buf) {
        const uint32_t ab = asm_u32 + buf * (HG_TILE * 2);
        const uint32_t bb = bsm_u32 + buf * (HG_TILE * 2);
        #pragma unroll
        for (int kk = 0; kk < 64; kk += 16) {
            uint32_t af[4][4], bf[2][4];
            #pragma unroll
            for (int mi = 0; mi < 4; mi++)
                ldmatrix_x4(af[mi],
                    ab + (((a_lrow + mi * 16) * HG_RS) + kk + a_lcol) * 2);
            #pragma unroll
            for (int pr = 0; pr < 2; pr++)
                ldmatrix_x4(bf[pr],
                    bb + (((b_lrow + pr * 16) * HG_RS) + kk + b_lcol) * 2);
            #pragma unroll
            for (int mi = 0; mi < 4; mi++)
                #pragma unroll
                for (int ni = 0; ni < 4; ni++)
                    mma_f16(acc[mi][ni], af[mi], bf[ni >> 1] + (ni & 1) * 2);
        }
    };

    // ---- synchronous double-buffered mainloop ----
    load_regs(0);
    store_regs(0);
    __syncthreads();

    for (int kt = 0; kt < NKT; kt++) {
        const int cur = kt & 1;
        if (kt + 1 < NKT) load_regs(kt + 1);
        compute_buf(cur);
        if (kt + 1 < NKT) store_regs(cur ^ 1);
        __syncthreads();
    }

    // ---- epilogue ----
    const float* Bp = Bias + (size_t)e * NN;
    float bias2[4][2];
    #pragma unroll
    for (int ni = 0; ni < 4; ni++) {
        const int col = col0 + wn * 32 + ni * 8 + c * 2;
        bias2[ni][0] = Bp[col];
        bias2[ni][1] = Bp[col + 1];
    }

    #pragma unroll
    for (int mi = 0; mi < 4; mi++) {
        #pragma unroll
        for (int h = 0; h < 2; h++) {
            const int rloc = row0 + wm * 64 + mi * 16 + r + h * 8;
            if (rloc >= m_count) continue;
            const size_t a_idx = (size_t)(m_base + rloc);
            if (MODE == 3) {
                float* dst = g_eout + a_idx * DD;
                const float scale = g_wgt[a_idx];
                #pragma unroll
                for (int ni = 0; ni < 4; ni++) {
                    const int col = col0 + wn * 32 + ni * 8 + c * 2;
                    const float v0 = (acc[mi][ni][h * 2 + 0] + bias2[ni][0]) * scale;
                    const float v1 = (acc[mi][ni][h * 2 + 1] + bias2[ni][1]) * scale;
                    *(float2*)(dst + col) = make_float2(v0, v1);
                }
            } else {
                __half* dst = ((MODE == 1) ? g_h1 : g_h2) + a_idx * HH;
                #pragma unroll
                for (int ni = 0; ni < 4; ni++) {
                    const int col = col0 + wn * 32 + ni * 8 + c * 2;
                    const float v0 = silu_precise(acc[mi][ni][h * 2 + 0] + bias2[ni][0]);
                    const float v1 = silu_precise(acc[mi][ni][h * 2 + 1] + bias2[ni][1]);
                    *(__half2*)(dst + col) = __floats2half2_rn(v0, v1);
                }
            }
        }
    }
}

// ---------------- router logits + top-2 softmax ------------------------------
__global__ __launch_bounds__(256)
void logits_topk_kernel(const float* __restrict__ Rw2, const float* __restrict__ Rb2)
{
    const int warp = (blockIdx.x * (blockDim.x >> 5)) + (threadIdx.x >> 5);
    if (warp >= BB) return;
    const int b = warp;
    const int lane = threadIdx.x & 31;

    float l[EE];
    #pragma unroll
    for (int e = 0; e < EE; e++) l[e] = 0.f;

    const float* __restrict__ hrow = g_h + (size_t)b * HH;
    for (int k = lane; k < HH; k += 32) {
        const float hv = hrow[k];
        const float4 w0 = *(const float4*)(Rw2 + (size_t)k * EE);
        const float4 w1 = *(const float4*)(Rw2 + (size_t)k * EE + 4);
        l[0] = fmaf(hv, w0.x, l[0]);
        l[1] = fmaf(hv, w0.y, l[1]);
        l[2] = fmaf(hv, w0.z, l[2]);
        l[3] = fmaf(hv, w0.w, l[3]);
        l[4] = fmaf(hv, w1.x, l[4]);
        l[5] = fmaf(hv, w1.y, l[5]);
        l[6] = fmaf(hv, w1.z, l[6]);
        l[7] = fmaf(hv, w1.w, l[7]);
    }
    #pragma unroll
    for (int off = 16; off > 0; off >>= 1)
        #pragma unroll
        for (int e = 0; e < EE; e++)
            l[e] += __shfl_xor_sync(0xffffffff, l[e], off);

    if (lane == 0) {
        #pragma unroll
        for (int e = 0; e < EE; e++) l[e] += Rb2[e];
        int i0 = 0;
        #pragma unroll
        for (int e = 1; e < EE; e++) if (l[e] > l[i0]) i0 = e;
        int i1 = (i0 == 0) ? 1 : 0;
        #pragma unroll
        for (int e = 0; e < EE; e++)
            if (e != i0 && l[e] > l[i1]) i1 = e;
        const float e1 = expf(l[i1] - l[i0]);
        const float inv = 1.f / (1.f + e1);
        g_topk_idx[b * 2 + 0] = i0;
        g_topk_idx[b * 2 + 1] = i1;
        g_topk_a[b * 2 + 0] = inv;
        g_topk_a[b * 2 + 1] = e1 * inv;
        atomicAdd(&g_cnt[i0], 1);
        atomicAdd(&g_cnt[i1], 1);
    }
}

// ---------------- bucket offsets ---------------------------------------------
__global__ void scan_kernel()
{
    if (threadIdx.x == 0) {
        int s = 0;
        for (int e = 0; e < EE; e++) {
            g_off[e] = s;
            g_cursor[e] = s;
            s += g_cnt[e];
        }
    }
}

// ---------------- scatter tokens into expert buckets -------------------------
__global__ __launch_bounds__(256)
void scatter_kernel()
{
    const int b = blockIdx.x * blockDim.x + threadIdx.x;
    if (b >= BB) return;
    #pragma unroll
    for (int j = 0; j < TOPK; j++) {
        const int e = g_topk_idx[b * 2 + j];
        const int pos = atomicAdd(&g_cursor[e], 1);
        g_perm[pos] = b;
        g_wgt[pos]  = g_topk_a[b * 2 + j];
        g_slot[b * 2 + j] = pos;
    }
}

// ---------------- deterministic 2-way combine --------------------------------
__global__ __launch_bounds__(256)
void combine_kernel(float* __restrict__ out)
{
    const int idx = blockIdx.x * blockDim.x + threadIdx.x;
    if (idx >= BB * DD / 4) return;
    const int b = idx / (DD / 4);
    const int q = idx % (DD / 4);
    const int s0 = g_slot[b * 2 + 0];
    const int s1 = g_slot[b * 2 + 1];
    const float4 v0 = *((const float4*)g_eout + (size_t)s0 * (DD / 4) + q);
    const float4 v1 = *((const float4*)g_eout + (size_t)s1 * (DD / 4) + q);
    ((float4*)out)[idx] = make_float4(v0.x + v1.x, v0.y + v1.y, v0.z + v1.z, v0.w + v1.w);
}

// ---------------- launch -----------------------------------------------------
extern "C" void kernel_launch(void* const* d_in, const int* in_sizes, int n_in,
                              void* d_out, int out_size)
{
    const float* t   = (const float*)d_in[0];
    const float* x   = (const float*)d_in[1];
    const float* Rw1 = (const float*)d_in[2];
    const float* Rb1 = (const float*)d_in[3];
    const float* Rw2 = (const float*)d_in[4];
    const float* Rb2 = (const float*)d_in[5];
    const float* Ew1 = (const float*)d_in[6];
    const float* Eb1 = (const float*)d_in[7];
    const float* Ew2 = (const float*)d_in[8];
    const float* Eb2 = (const float*)d_in[9];
    const float* Ew3 = (const float*)d_in[10];
    const float* Eb3 = (const float*)d_in[11];
    float* out = (float*)d_out;

    cudaFuncSetAttribute(hgemm5_kernel<1>, cudaFuncAttributeMaxDynamicSharedMemorySize, HG_SMEM_BYTES);
    cudaFuncSetAttribute(hgemm5_kernel<2>, cudaFuncAttributeMaxDynamicSharedMemorySize, HG_SMEM_BYTES);
    cudaFuncSetAttribute(hgemm5_kernel<3>, cudaFuncAttributeMaxDynamicSharedMemorySize, HG_SMEM_BYTES);

    reset_kernel<<<1, 32>>>();

    // pre-pass: half conversions; all destinations resolved device-side
    pack_x_kernel<<<(BB * (KP1 / 2) + 255) / 256, 256>>>(x, t);
    convert_w_kernel<1><<<dim3(HH / 32, KP1 / 32, EE), dim3(32, 8)>>>(Ew1, KXT, HH, KP1);
    convert_w_kernel<2><<<dim3(HH / 32, HH / 32, EE), dim3(32, 8)>>>(Ew2, HH, HH, HH);
    convert_w_kernel<3><<<dim3(DD / 32, HH / 32, EE), dim3(32, 8)>>>(Ew3, HH, DD, HH);

    // router hidden: exact fp32 (gating selection must match reference)
    router_gemm_kernel<<<dim3(HH / 128, BB / 128, 1), 256>>>(x, t, Rw1, Rb1);

    // logits + top-2 softmax gate (exact fp32)
    logits_topk_kernel<<<BB / 8, 256>>>(Rw2, Rb2);
    scan_kernel<<<1, 32>>>();
    scatter_kernel<<<BB / 256, 256>>>();

    // grouped expert MLP: fp16 mma.sync + ldmatrix, n-major half weights
    hgemm5_kernel<1><<<dim3(HH / 128, 256, EE), 256, HG_SMEM_BYTES>>>(Eb1);
    hgemm5_kernel<2><<<dim3(HH / 128, 256, EE), 256, HG_SMEM_BYTES>>>(Eb2);
    hgemm5_kernel<3><<<dim3(DD / 128, 256, EE), 256, HG_SMEM_BYTES>>>(Eb3);

    // out[b] = alpha0*eout[slot0] + alpha1*eout[slot1]
    combine_kernel<<<(BB * DD / 4 + 255) / 256, 256>>>(out);
}

// round 16
// speedup vs baseline: 5.8282x; 1.2272x over previous
#include <cuda_runtime.h>
#include <cuda_fp16.h>
#include <cstdint>

#define BB 16384
#define DD 256
#define HH 1024
#define EE 8
#define KXT 257   // D+1
#define TOPK 2
#define KP1 320   // K of fc1 padded to 5*64

// ---------------- scratch (static device memory; no allocations) -------------
// RULE: device symbols are ONLY dereferenced from device code (ATS shadow bug).
__device__ float  g_h[(size_t)BB * HH];
__device__ __align__(16) __half g_xh[(size_t)BB * KP1];
__device__ __align__(16) __half g_w1t[(size_t)EE * HH * KP1];  // [E][N][Kpad]
__device__ __align__(16) __half g_w2t[(size_t)EE * HH * HH];   // [E][N][K]
__device__ __align__(16) __half g_w3t[(size_t)EE * DD * HH];   // [E][N][K]
__device__ __align__(16) __half g_h1[(size_t)2 * BB * HH];
__device__ __align__(16) __half g_h2[(size_t)2 * BB * HH];
__device__ float  g_eout[(size_t)2 * BB * DD];
__device__ int    g_perm[2 * BB];
__device__ float  g_wgt[2 * BB];
__device__ int    g_slot[2 * BB];
__device__ int    g_topk_idx[BB * TOPK];
__device__ float  g_topk_a[BB * TOPK];
__device__ int    g_cnt[EE];
__device__ int    g_off[EE];
__device__ int    g_cursor[EE];

__device__ __forceinline__ float silu_precise(float v) {
    return v / (1.f + expf(-v));
}

__device__ __forceinline__ uint32_t smem_u32(const void* p) {
    uint32_t a;
    asm("{ .reg .u64 t; cvta.to.shared.u64 t, %1; cvt.u32.u64 %0, t; }"
        : "=r"(a) : "l"(p));
    return a;
}

__device__ __forceinline__ void cp_async16(uint32_t dst, const void* src, uint32_t src_bytes) {
    asm volatile("cp.async.cg.shared.global [%0], [%1], 16, %2;"
                 :: "r"(dst), "l"(src), "r"(src_bytes) : "memory");
}
__device__ __forceinline__ void cp_commit() {
    asm volatile("cp.async.commit_group;" ::: "memory");
}
template <int N>
__device__ __forceinline__ void cp_wait() {
    asm volatile("cp.async.wait_group %0;" :: "n"(N) : "memory");
}

__device__ __forceinline__ void ldmatrix_x4(uint32_t* r, uint32_t addr) {
    asm volatile("ldmatrix.sync.aligned.m8n8.x4.shared.b16 {%0,%1,%2,%3}, [%4];"
                 : "=r"(r[0]), "=r"(r[1]), "=r"(r[2]), "=r"(r[3]) : "r"(addr));
}

__device__ __forceinline__ void mma_f16(float* d, const uint32_t* a, const uint32_t* b) {
    asm volatile(
        "mma.sync.aligned.m16n8k16.row.col.f32.f16.f16.f32 "
        "{%0,%1,%2,%3}, {%4,%5,%6,%7}, {%8,%9}, {%0,%1,%2,%3};"
        : "+f"(d[0]), "+f"(d[1]), "+f"(d[2]), "+f"(d[3])
        : "r"(a[0]), "r"(a[1]), "r"(a[2]), "r"(a[3]), "r"(b[0]), "r"(b[1]));
}

// ---------------- reset ------------------------------------------------------
__global__ void reset_kernel() {
    if (threadIdx.x < EE) g_cnt[threadIdx.x] = 0;
}

// ---------------- pre-pass: pack [x|t] to half, K-padded ---------------------
__global__ __launch_bounds__(256)
void pack_x_kernel(const float* __restrict__ X, const float* __restrict__ T)
{
    const int i = blockIdx.x * 256 + threadIdx.x;   // half2 index
    if (i >= BB * (KP1 / 2)) return;
    const int b = i / (KP1 / 2);
    const int k = (i % (KP1 / 2)) * 2;
    __half2 h;
    if (k + 1 < DD) {
        const float2 v = *(const float2*)(X + (size_t)b * DD + k);
        h = __floats2half2_rn(v.x, v.y);
    } else if (k == DD) {
        h = __floats2half2_rn(T[b], 0.f);
    } else {
        h = __floats2half2_rn(0.f, 0.f);
    }
    *((__half2*)g_xh + i) = h;
}

// ---------------- pre-pass: transpose-convert weights to half [E][N][KPad] ---
template <int WS>
__global__ __launch_bounds__(256)
void convert_w_kernel(const float* __restrict__ W, int K, int N, int KPad)
{
    __half* __restrict__ Wh = (WS == 1) ? g_w1t : (WS == 2) ? g_w2t : g_w3t;
    __shared__ float tile[32][33];
    const int e  = blockIdx.z;
    const float* Wp = W + (size_t)e * K * N;
    __half* Whp = Wh + (size_t)e * N * KPad;
    const int n0 = blockIdx.x * 32;
    const int k0 = blockIdx.y * 32;
    const int tx = threadIdx.x, ty = threadIdx.y;
    #pragma unroll
    for (int i = 0; i < 4; i++) {
        const int k = k0 + ty + i * 8;
        const int n = n0 + tx;
        tile[ty + i * 8][tx] = (k < K) ? Wp[(size_t)k * N + n] : 0.f;
    }
    __syncthreads();
    #pragma unroll
    for (int i = 0; i < 4; i++) {
        const int n = n0 + ty + i * 8;
        const int k = k0 + tx;
        if (k < KPad) Whp[(size_t)n * KPad + k] = __float2half_rn(tile[tx][ty + i * 8]);
    }
}

// ---------------- fp32 router GEMM (exact; gating must match reference) ------
__global__ __launch_bounds__(256)
void router_gemm_kernel(const float* __restrict__ X, const float* __restrict__ T,
                        const float* __restrict__ W, const float* __restrict__ Bias)
{
    constexpr int KK = KXT, NN = HH;
    constexpr int BM = 128, BN = 128, BK = 8;
    constexpr int NKT = (KK + BK - 1) / BK;

    const int row0 = blockIdx.y * BM;
    const int col0 = blockIdx.x * BN;

    __shared__ __align__(16) float As[BK][BM + 4];
    __shared__ __align__(16) float Bs[BK][BN + 4];

    const int tid = threadIdx.x;
    const int tx = tid & 15;
    const int ty = tid >> 4;
    const int a_row = tid >> 1;
    const int a_k4  = (tid & 1) * 4;
    const int b_k  = tid >> 5;
    const int b_n  = (tid & 31) * 4;

    const int tok = row0 + a_row;

    float acc[8][8];
    #pragma unroll
    for (int i = 0; i < 8; i++)
        #pragma unroll
        for (int j = 0; j < 8; j++) acc[i][j] = 0.f;

    for (int kt = 0; kt < NKT; kt++) {
        const int kb = kt * BK;
        #pragma unroll
        for (int l = 0; l < 4; l++) {
            const int k = kb + a_k4 + l;
            float v = 0.f;
            if (k < DD)       v = X[(size_t)tok * DD + k];
            else if (k == DD) v = T[tok];
            As[a_k4 + l][a_row] = v;
        }
        {
            const int k = kb + b_k;
            float4 v = make_float4(0.f, 0.f, 0.f, 0.f);
            if (k < KK) v = *(const float4*)(W + (size_t)k * NN + col0 + b_n);
            Bs[b_k][b_n + 0] = v.x;
            Bs[b_k][b_n + 1] = v.y;
            Bs[b_k][b_n + 2] = v.z;
            Bs[b_k][b_n + 3] = v.w;
        }
        __syncthreads();
        #pragma unroll
        for (int k = 0; k < BK; k++) {
            float a[8], b[8];
            *(float4*)(a)     = *(const float4*)&As[k][ty * 8];
            *(float4*)(a + 4) = *(const float4*)&As[k][ty * 8 + 4];
            *(float4*)(b)     = *(const float4*)&Bs[k][tx * 8];
            *(float4*)(b + 4) = *(const float4*)&Bs[k][tx * 8 + 4];
            #pragma unroll
            for (int i = 0; i < 8; i++)
                #pragma unroll
                for (int j = 0; j < 8; j++)
                    acc[i][j] = fmaf(a[i], b[j], acc[i][j]);
        }
        __syncthreads();
    }

    float bias[8];
    #pragma unroll
    for (int j = 0; j < 8; j++) bias[j] = Bias[col0 + tx * 8 + j];

    #pragma unroll
    for (int i = 0; i < 8; i++) {
        const int rloc = row0 + ty * 8 + i;
        float* dst = g_h + (size_t)rloc * HH;
        float tmp[8];
        #pragma unroll
        for (int j = 0; j < 8; j++)
            tmp[j] = silu_precise(acc[i][j] + bias[j]);
        *(float4*)(dst + col0 + tx * 8)     = make_float4(tmp[0], tmp[1], tmp[2], tmp[3]);
        *(float4*)(dst + col0 + tx * 8 + 4) = make_float4(tmp[4], tmp[5], tmp[6], tmp[7]);
    }
}

// ---------------- FP16 mma.sync grouped GEMM, 3-stage cp.async ---------------
// Same loader coverage / fragments / epilogue as the PASSING R15 kernel.
// Pipeline: one commit per iteration (empty on tail) => at iteration kt the
// pending set is {G(kt), G(kt+1)}; wait_group<1> completes G(kt).
// MODE 1: fc1 : A = g_xh rows via g_perm (Kpad=320), W=g_w1t, silu  -> g_h1
// MODE 2: fc2 : A = g_h1 (K=1024),                   W=g_w2t, silu  -> g_h2
// MODE 3: fc3 : A = g_h2 (K=1024),                   W=g_w3t, *alpha-> g_eout
#define HG_STAGES 3
#define HG_RS 72                       // 64 + 8 halves (144B row stride)
#define HG_TILE (128 * HG_RS)          // halves per (A or B) stage tile
#define HG_TILE_B (HG_TILE * 2)        // bytes per stage tile
#define HG_SMEM_BYTES (HG_STAGES * HG_TILE_B * 2)   // A+B stages = 110592 B

template <int MODE>
__global__ __launch_bounds__(256, 2)
void hgemm6_kernel(const float* __restrict__ Bias)
{
    constexpr int KPAD = (MODE == 1) ? KP1 : HH;
    constexpr int NN   = (MODE == 3) ? DD : HH;
    constexpr int NKT  = KPAD / 64;

    const int e = blockIdx.z;
    const int m_base  = g_off[e];
    const int m_count = g_cnt[e];
    const int row0 = blockIdx.y * 128;
    if (row0 >= m_count) return;
    const int col0 = blockIdx.x * 128;

    extern __shared__ __half smem[];
    __half* Asm = smem;                              // [S][HG_TILE]
    __half* Bsm = smem + HG_STAGES * HG_TILE;        // [S][HG_TILE]

    const int tid  = threadIdx.x;
    const int warp = tid >> 5;
    const int lane = tid & 31;
    const int wm = warp >> 2;       // 0..1 : 64-row slab
    const int wn = warp & 3;        // 0..3 : 32-col slab
    const int r  = lane >> 2;       // 0..7
    const int c  = lane & 3;        // 0..3

    // ---- loader: rows {lrow, lrow+64} x k-chunks {lc16*8, lc16*8+32} --------
    const int lrow = tid >> 2;      // 0..63
    const int lc16 = tid & 3;       // 0..3

    const __half* srcA[2];
    uint32_t szA[2];
    const __half* Wg =
        (MODE == 1) ? g_w1t : (MODE == 2) ? g_w2t : g_w3t;
    const __half* Wbase = Wg + (size_t)e * NN * KPAD + (size_t)col0 * KPAD;
    const __half* srcB[2];

    #pragma unroll
    for (int i = 0; i < 2; i++) {
        const int rowi = lrow + i * 64;
        const int rloc = row0 + rowi;
        const bool valid = rloc < m_count;
        const __half* p;
        if (MODE == 1)      p = g_xh + (valid ? (size_t)g_perm[m_base + rloc] * KP1 : 0);
        else if (MODE == 2) p = g_h1 + (valid ? (size_t)(m_base + rloc) * HH : 0);
        else                p = g_h2 + (valid ? (size_t)(m_base + rloc) * HH : 0);
        srcA[i] = p + lc16 * 8;
        szA[i]  = valid ? 16u : 0u;    // src_size 0 => cp.async zero-fills
        srcB[i] = Wbase + (size_t)rowi * KPAD + lc16 * 8;
    }
    const uint32_t dstoff_b[2] = {
        (uint32_t)((lrow * HG_RS + lc16 * 8) * 2),
        (uint32_t)(((lrow + 64) * HG_RS + lc16 * 8) * 2) };

    const uint32_t asm_u32 = smem_u32(Asm);
    const uint32_t bsm_u32 = smem_u32(Bsm);

    auto load_stage = [&](int s, int kt) {
        const uint32_t ab = asm_u32 + s * HG_TILE_B;
        const uint32_t bb = bsm_u32 + s * HG_TILE_B;
        const int koff = kt * 64;
        #pragma unroll
        for (int i = 0; i < 2; i++) {
            cp_async16(ab + dstoff_b[i],      srcA[i] + koff,      szA[i]);
            cp_async16(ab + dstoff_b[i] + 64, srcA[i] + koff + 32, szA[i]);
            cp_async16(bb + dstoff_b[i],      srcB[i] + koff,      16u);
            cp_async16(bb + dstoff_b[i] + 64, srcB[i] + koff + 32, 16u);
        }
        cp_commit();
    };

    float acc[4][4][4];
    #pragma unroll
    for (int mi = 0; mi < 4; mi++)
        #pragma unroll
        for (int ni = 0; ni < 4; ni++)
            #pragma unroll
            for (int q = 0; q < 4; q++) acc[mi][ni][q] = 0.f;

    // ldmatrix lane addressing (element offsets within a tile)
    const int a_lrow = wm * 64 + (lane & 15);
    const int a_lcol = (lane >> 4) * 8;
    const int b_lrow = wn * 32 + ((lane >> 4) & 1) * 8 + (lane & 7);
    const int b_lcol = ((lane >> 3) & 1) * 8;

    auto compute_stage = [&](int s) {
        const uint32_t ab = asm_u32 + s * HG_TILE_B;
        const uint32_t bb = bsm_u32 + s * HG_TILE_B;
        #pragma unroll
        for (int kk = 0; kk < 64; kk += 16) {
            uint32_t af[4][4], bf[2][4];
            #pragma unroll
            for (int mi = 0; mi < 4; mi++)
                ldmatrix_x4(af[mi],
                    ab + (((a_lrow + mi * 16) * HG_RS) + kk + a_lcol) * 2);
            #pragma unroll
            for (int pr = 0; pr < 2; pr++)
                ldmatrix_x4(bf[pr],
                    bb + (((b_lrow + pr * 16) * HG_RS) + kk + b_lcol) * 2);
            #pragma unroll
            for (int mi = 0; mi < 4; mi++)
                #pragma unroll
                for (int ni = 0; ni < 4; ni++)
                    mma_f16(acc[mi][ni], af[mi], bf[ni >> 1] + (ni & 1) * 2);
        }
    };

    // ---- 3-stage pipeline ----
    load_stage(0, 0);
    if (NKT > 1) load_stage(1, 1);
    else         cp_commit();

    for (int kt = 0; kt < NKT; kt++) {
        cp_wait<1>();
        __syncthreads();
        const int ktn = kt + 2;
        if (ktn < NKT) load_stage(ktn % HG_STAGES, ktn);
        else           cp_commit();
        compute_stage(kt % HG_STAGES);
    }

    // ---- epilogue ----
    const float* Bp = Bias + (size_t)e * NN;
    float bias2[4][2];
    #pragma unroll
    for (int ni = 0; ni < 4; ni++) {
        const int col = col0 + wn * 32 + ni * 8 + c * 2;
        bias2[ni][0] = Bp[col];
        bias2[ni][1] = Bp[col + 1];
    }

    #pragma unroll
    for (int mi = 0; mi < 4; mi++) {
        #pragma unroll
        for (int h = 0; h < 2; h++) {
            const int rloc = row0 + wm * 64 + mi * 16 + r + h * 8;
            if (rloc >= m_count) continue;
            const size_t a_idx = (size_t)(m_base + rloc);
            if (MODE == 3) {
                float* dst = g_eout + a_idx * DD;
                const float scale = g_wgt[a_idx];
                #pragma unroll
                for (int ni = 0; ni < 4; ni++) {
                    const int col = col0 + wn * 32 + ni * 8 + c * 2;
                    const float v0 = (acc[mi][ni][h * 2 + 0] + bias2[ni][0]) * scale;
                    const float v1 = (acc[mi][ni][h * 2 + 1] + bias2[ni][1]) * scale;
                    *(float2*)(dst + col) = make_float2(v0, v1);
                }
            } else {
                __half* dst = ((MODE == 1) ? g_h1 : g_h2) + a_idx * HH;
                #pragma unroll
                for (int ni = 0; ni < 4; ni++) {
                    const int col = col0 + wn * 32 + ni * 8 + c * 2;
                    const float v0 = silu_precise(acc[mi][ni][h * 2 + 0] + bias2[ni][0]);
                    const float v1 = silu_precise(acc[mi][ni][h * 2 + 1] + bias2[ni][1]);
                    *(__half2*)(dst + col) = __floats2half2_rn(v0, v1);
                }
            }
        }
    }
}

// ---------------- router logits + top-2 softmax ------------------------------
__global__ __launch_bounds__(256)
void logits_topk_kernel(const float* __restrict__ Rw2, const float* __restrict__ Rb2)
{
    const int warp = (blockIdx.x * (blockDim.x >> 5)) + (threadIdx.x >> 5);
    if (warp >= BB) return;
    const int b = warp;
    const int lane = threadIdx.x & 31;

    float l[EE];
    #pragma unroll
    for (int e = 0; e < EE; e++) l[e] = 0.f;

    const float* __restrict__ hrow = g_h + (size_t)b * HH;
    for (int k = lane; k < HH; k += 32) {
        const float hv = hrow[k];
        const float4 w0 = *(const float4*)(Rw2 + (size_t)k * EE);
        const float4 w1 = *(const float4*)(Rw2 + (size_t)k * EE + 4);
        l[0] = fmaf(hv, w0.x, l[0]);
        l[1] = fmaf(hv, w0.y, l[1]);
        l[2] = fmaf(hv, w0.z, l[2]);
        l[3] = fmaf(hv, w0.w, l[3]);
        l[4] = fmaf(hv, w1.x, l[4]);
        l[5] = fmaf(hv, w1.y, l[5]);
        l[6] = fmaf(hv, w1.z, l[6]);
        l[7] = fmaf(hv, w1.w, l[7]);
    }
    #pragma unroll
    for (int off = 16; off > 0; off >>= 1)
        #pragma unroll
        for (int e = 0; e < EE; e++)
            l[e] += __shfl_xor_sync(0xffffffff, l[e], off);

    if (lane == 0) {
        #pragma unroll
        for (int e = 0; e < EE; e++) l[e] += Rb2[e];
        int i0 = 0;
        #pragma unroll
        for (int e = 1; e < EE; e++) if (l[e] > l[i0]) i0 = e;
        int i1 = (i0 == 0) ? 1 : 0;
        #pragma unroll
        for (int e = 0; e < EE; e++)
            if (e != i0 && l[e] > l[i1]) i1 = e;
        const float e1 = expf(l[i1] - l[i0]);
        const float inv = 1.f / (1.f + e1);
        g_topk_idx[b * 2 + 0] = i0;
        g_topk_idx[b * 2 + 1] = i1;
        g_topk_a[b * 2 + 0] = inv;
        g_topk_a[b * 2 + 1] = e1 * inv;
        atomicAdd(&g_cnt[i0], 1);
        atomicAdd(&g_cnt[i1], 1);
    }
}

// ---------------- bucket offsets ---------------------------------------------
__global__ void scan_kernel()
{
    if (threadIdx.x == 0) {
        int s = 0;
        for (int e = 0; e < EE; e++) {
            g_off[e] = s;
            g_cursor[e] = s;
            s += g_cnt[e];
        }
    }
}

// ---------------- scatter tokens into expert buckets -------------------------
__global__ __launch_bounds__(256)
void scatter_kernel()
{
    const int b = blockIdx.x * blockDim.x + threadIdx.x;
    if (b >= BB) return;
    #pragma unroll
    for (int j = 0; j < TOPK; j++) {
        const int e = g_topk_idx[b * 2 + j];
        const int pos = atomicAdd(&g_cursor[e], 1);
        g_perm[pos] = b;
        g_wgt[pos]  = g_topk_a[b * 2 + j];
        g_slot[b * 2 + j] = pos;
    }
}

// ---------------- deterministic 2-way combine --------------------------------
__global__ __launch_bounds__(256)
void combine_kernel(float* __restrict__ out)
{
    const int idx = blockIdx.x * blockDim.x + threadIdx.x;
    if (idx >= BB * DD / 4) return;
    const int b = idx / (DD / 4);
    const int q = idx % (DD / 4);
    const int s0 = g_slot[b * 2 + 0];
    const int s1 = g_slot[b * 2 + 1];
    const float4 v0 = *((const float4*)g_eout + (size_t)s0 * (DD / 4) + q);
    const float4 v1 = *((const float4*)g_eout + (size_t)s1 * (DD / 4) + q);
    ((float4*)out)[idx] = make_float4(v0.x + v1.x, v0.y + v1.y, v0.z + v1.z, v0.w + v1.w);
}

// ---------------- launch -----------------------------------------------------
extern "C" void kernel_launch(void* const* d_in, const int* in_sizes, int n_in,
                              void* d_out, int out_size)
{
    const float* t   = (const float*)d_in[0];
    const float* x   = (const float*)d_in[1];
    const float* Rw1 = (const float*)d_in[2];
    const float* Rb1 = (const float*)d_in[3];
    const float* Rw2 = (const float*)d_in[4];
    const float* Rb2 = (const float*)d_in[5];
    const float* Ew1 = (const float*)d_in[6];
    const float* Eb1 = (const float*)d_in[7];
    const float* Ew2 = (const float*)d_in[8];
    const float* Eb2 = (const float*)d_in[9];
    const float* Ew3 = (const float*)d_in[10];
    const float* Eb3 = (const float*)d_in[11];
    float* out = (float*)d_out;

    cudaFuncSetAttribute(hgemm6_kernel<1>, cudaFuncAttributeMaxDynamicSharedMemorySize, HG_SMEM_BYTES);
    cudaFuncSetAttribute(hgemm6_kernel<2>, cudaFuncAttributeMaxDynamicSharedMemorySize, HG_SMEM_BYTES);
    cudaFuncSetAttribute(hgemm6_kernel<3>, cudaFuncAttributeMaxDynamicSharedMemorySize, HG_SMEM_BYTES);

    reset_kernel<<<1, 32>>>();

    // pre-pass: half conversions; all destinations resolved device-side
    pack_x_kernel<<<(BB * (KP1 / 2) + 255) / 256, 256>>>(x, t);
    convert_w_kernel<1><<<dim3(HH / 32, KP1 / 32, EE), dim3(32, 8)>>>(Ew1, KXT, HH, KP1);
    convert_w_kernel<2><<<dim3(HH / 32, HH / 32, EE), dim3(32, 8)>>>(Ew2, HH, HH, HH);
    convert_w_kernel<3><<<dim3(DD / 32, HH / 32, EE), dim3(32, 8)>>>(Ew3, HH, DD, HH);

    // router hidden: exact fp32 (gating selection must match reference)
    router_gemm_kernel<<<dim3(HH / 128, BB / 128, 1), 256>>>(x, t, Rw1, Rb1);

    // logits + top-2 softmax gate (exact fp32)
    logits_topk_kernel<<<BB / 8, 256>>>(Rw2, Rb2);
    scan_kernel<<<1, 32>>>();
    scatter_kernel<<<BB / 256, 256>>>();

    // grouped expert MLP: fp16 mma.sync + ldmatrix + 3-stage cp.async
    hgemm6_kernel<1><<<dim3(HH / 128, 256, EE), 256, HG_SMEM_BYTES>>>(Eb1);
    hgemm6_kernel<2><<<dim3(HH / 128, 256, EE), 256, HG_SMEM_BYTES>>>(Eb2);
    hgemm6_kernel<3><<<dim3(DD / 128, 256, EE), 256, HG_SMEM_BYTES>>>(Eb3);

    // out[b] = alpha0*eout[slot0] + alpha1*eout[slot1]
    combine_kernel<<<(BB * DD / 4 + 255) / 256, 256>>>(out);
}

// round 17
// speedup vs baseline: 7.3330x; 1.2582x over previous
#include <cuda_runtime.h>
#include <cuda_fp16.h>
#include <cstdint>

#define BB 16384
#define DD 256
#define HH 1024
#define EE 8
#define KXT 257   // D+1
#define TOPK 2
#define KP1 320   // K of fc1 padded to 5*64

// ---------------- scratch (static device memory; no allocations) -------------
// RULE: device symbols are ONLY dereferenced from device code (ATS shadow bug).
__device__ float  g_h[(size_t)BB * HH];
__device__ __align__(16) __half g_xh[(size_t)BB * KP1];        // hi([x|t]) K-padded
__device__ __align__(16) __half g_xlo[(size_t)BB * KP1];       // lo([x|t])
__device__ __align__(16) __half g_rw1hi[(size_t)HH * KP1];     // Rw1 hi, [N][Kpad]
__device__ __align__(16) __half g_rw1lo[(size_t)HH * KP1];     // Rw1 lo, [N][Kpad]
__device__ __align__(16) __half g_w1t[(size_t)EE * HH * KP1];  // [E][N][Kpad]
__device__ __align__(16) __half g_w2t[(size_t)EE * HH * HH];   // [E][N][K]
__device__ __align__(16) __half g_w3t[(size_t)EE * DD * HH];   // [E][N][K]
__device__ __align__(16) __half g_h1[(size_t)2 * BB * HH];
__device__ __align__(16) __half g_h2[(size_t)2 * BB * HH];
__device__ float  g_eout[(size_t)2 * BB * DD];
__device__ int    g_perm[2 * BB];
__device__ float  g_wgt[2 * BB];
__device__ int    g_slot[2 * BB];
__device__ int    g_topk_idx[BB * TOPK];
__device__ float  g_topk_a[BB * TOPK];
__device__ int    g_cnt[EE];
__device__ int    g_off[EE];
__device__ int    g_cursor[EE];

__device__ __forceinline__ float silu_precise(float v) {
    return v / (1.f + expf(-v));
}

__device__ __forceinline__ uint32_t smem_u32(const void* p) {
    uint32_t a;
    asm("{ .reg .u64 t; cvta.to.shared.u64 t, %1; cvt.u32.u64 %0, t; }"
        : "=r"(a) : "l"(p));
    return a;
}

__device__ __forceinline__ void cp_async16(uint32_t dst, const void* src, uint32_t src_bytes) {
    asm volatile("cp.async.cg.shared.global [%0], [%1], 16, %2;"
                 :: "r"(dst), "l"(src), "r"(src_bytes) : "memory");
}
__device__ __forceinline__ void cp_commit() {
    asm volatile("cp.async.commit_group;" ::: "memory");
}
template <int N>
__device__ __forceinline__ void cp_wait() {
    asm volatile("cp.async.wait_group %0;" :: "n"(N) : "memory");
}

__device__ __forceinline__ void ldmatrix_x4(uint32_t* r, uint32_t addr) {
    asm volatile("ldmatrix.sync.aligned.m8n8.x4.shared.b16 {%0,%1,%2,%3}, [%4];"
                 : "=r"(r[0]), "=r"(r[1]), "=r"(r[2]), "=r"(r[3]) : "r"(addr));
}

__device__ __forceinline__ void mma_f16(float* d, const uint32_t* a, const uint32_t* b) {
    asm volatile(
        "mma.sync.aligned.m16n8k16.row.col.f32.f16.f16.f32 "
        "{%0,%1,%2,%3}, {%4,%5,%6,%7}, {%8,%9}, {%0,%1,%2,%3};"
        : "+f"(d[0]), "+f"(d[1]), "+f"(d[2]), "+f"(d[3])
        : "r"(a[0]), "r"(a[1]), "r"(a[2]), "r"(a[3]), "r"(b[0]), "r"(b[1]));
}

// ---------------- reset ------------------------------------------------------
__global__ void reset_kernel() {
    if (threadIdx.x < EE) g_cnt[threadIdx.x] = 0;
}

// ---------------- pre-pass: split [x|t] into fp16 hi/lo, K-padded ------------
__global__ __launch_bounds__(256)
void pack_x_split_kernel(const float* __restrict__ X, const float* __restrict__ T)
{
    const int i = blockIdx.x * 256 + threadIdx.x;
    if (i >= BB * KP1) return;
    const int b = i / KP1;
    const int k = i % KP1;
    float v = 0.f;
    if (k < DD)       v = X[(size_t)b * DD + k];
    else if (k == DD) v = T[b];
    const __half hi = __float2half_rn(v);
    const __half lo = __float2half_rn(v - __half2float(hi));
    g_xh[i]  = hi;
    g_xlo[i] = lo;
}

// ---------------- pre-pass: Rw1 -> hi/lo, n-major [N][KPad] ------------------
__global__ __launch_bounds__(256)
void convert_r1_kernel(const float* __restrict__ W)   // W: [KXT][HH]
{
    __shared__ float tile[32][33];
    const int n0 = blockIdx.x * 32;
    const int k0 = blockIdx.y * 32;
    const int tx = threadIdx.x, ty = threadIdx.y;
    #pragma unroll
    for (int i = 0; i < 4; i++) {
        const int k = k0 + ty + i * 8;
        tile[ty + i * 8][tx] = (k < KXT) ? W[(size_t)k * HH + n0 + tx] : 0.f;
    }
    __syncthreads();
    #pragma unroll
    for (int i = 0; i < 4; i++) {
        const int n = n0 + ty + i * 8;
        const int k = k0 + tx;
        if (k < KP1) {
            const float v = tile[tx][ty + i * 8];
            const __half hi = __float2half_rn(v);
            const __half lo = __float2half_rn(v - __half2float(hi));
            g_rw1hi[(size_t)n * KP1 + k] = hi;
            g_rw1lo[(size_t)n * KP1 + k] = lo;
        }
    }
}

// ---------------- pre-pass: expert weights -> half, n-major [E][N][KPad] -----
template <int WS>
__global__ __launch_bounds__(256)
void convert_w_kernel(const float* __restrict__ W, int K, int N, int KPad)
{
    __half* __restrict__ Wh = (WS == 1) ? g_w1t : (WS == 2) ? g_w2t : g_w3t;
    __shared__ float tile[32][33];
    const int e  = blockIdx.z;
    const float* Wp = W + (size_t)e * K * N;
    __half* Whp = Wh + (size_t)e * N * KPad;
    const int n0 = blockIdx.x * 32;
    const int k0 = blockIdx.y * 32;
    const int tx = threadIdx.x, ty = threadIdx.y;
    #pragma unroll
    for (int i = 0; i < 4; i++) {
        const int k = k0 + ty + i * 8;
        const int n = n0 + tx;
        tile[ty + i * 8][tx] = (k < K) ? Wp[(size_t)k * N + n] : 0.f;
    }
    __syncthreads();
    #pragma unroll
    for (int i = 0; i < 4; i++) {
        const int n = n0 + ty + i * 8;
        const int k = k0 + tx;
        if (k < KPad) Whp[(size_t)n * KPad + k] = __float2half_rn(tile[tx][ty + i * 8]);
    }
}

// ---------------- router GEMM: split-fp16 (hi/lo), ~fp32-accurate ------------
// h = silu(xt @ Rw1 + Rb1), computed as hi*Whi + hi*Wlo + lo*Whi in fp16 mma
// with fp32 accumulation. Dropped lo*lo term ~ 2^-22 rel: below the fp32
// reordering noise already present vs the reference. Gating stays exact fp32.
// BK=32 (RS=40, conflict-free ldmatrix), 2-stage cp.async, 2 CTAs/SM.
#define RG_RS 40
#define RG_TILE (128 * RG_RS)          // halves per array tile
#define RG_TILE_B (RG_TILE * 2)        // bytes
#define RG_SMEM_BYTES (2 * 4 * RG_TILE_B)   // 2 stages x {Ahi,Alo,Bhi,Blo} = 81920

__global__ __launch_bounds__(256, 2)
void router_split_kernel(const float* __restrict__ Rb1)
{
    constexpr int NKT = KP1 / 32;      // 10

    const int row0 = blockIdx.y * 128;
    const int col0 = blockIdx.x * 128;

    extern __shared__ __half smem[];
    // layout: [stage][arr(Ahi=0,Alo=1,Bhi=2,Blo=3)][RG_TILE]
    const uint32_t smem_base = smem_u32(smem);

    const int tid  = threadIdx.x;
    const int warp = tid >> 5;
    const int lane = tid & 31;
    const int wm = warp >> 2;
    const int wn = warp & 3;
    const int r  = lane >> 2;
    const int c  = lane & 3;

    // loader: row lrow (0..127), half-offset hoff in {0,16}; chunks hoff, hoff+8
    const int lrow = tid >> 1;
    const int hoff = (tid & 1) * 16;

    const __half* srcs[4] = {
        g_xh    + (size_t)(row0 + lrow) * KP1 + hoff,
        g_xlo   + (size_t)(row0 + lrow) * KP1 + hoff,
        g_rw1hi + (size_t)(col0 + lrow) * KP1 + hoff,
        g_rw1lo + (size_t)(col0 + lrow) * KP1 + hoff };
    const uint32_t d0 = (uint32_t)((lrow * RG_RS + hoff) * 2);

    auto load_stage = [&](int s, int kt) {
        const int koff = kt * 32;
        #pragma unroll
        for (int a = 0; a < 4; a++) {
            const uint32_t base = smem_base + (s * 4 + a) * RG_TILE_B;
            cp_async16(base + d0,      srcs[a] + koff,     16u);
            cp_async16(base + d0 + 16, srcs[a] + koff + 8, 16u);
        }
        cp_commit();
    };

    float acc[4][4][4];
    #pragma unroll
    for (int mi = 0; mi < 4; mi++)
        #pragma unroll
        for (int ni = 0; ni < 4; ni++)
            #pragma unroll
            for (int q = 0; q < 4; q++) acc[mi][ni][q] = 0.f;

    const int a_lrow = wm * 64 + (lane & 15);
    const int a_lcol = (lane >> 4) * 8;
    const int b_lrow = wn * 32 + ((lane >> 4) & 1) * 8 + (lane & 7);
    const int b_lcol = ((lane >> 3) & 1) * 8;

    auto compute_stage = [&](int s) {
        const uint32_t ahi = smem_base + (s * 4 + 0) * RG_TILE_B;
        const uint32_t alo = smem_base + (s * 4 + 1) * RG_TILE_B;
        const uint32_t bhi = smem_base + (s * 4 + 2) * RG_TILE_B;
        const uint32_t blo = smem_base + (s * 4 + 3) * RG_TILE_B;
        #pragma unroll
        for (int kk = 0; kk < 32; kk += 16) {
            uint32_t afh[4][4], afl[4][4], bfh[2][4], bfl[2][4];
            #pragma unroll
            for (int mi = 0; mi < 4; mi++) {
                const uint32_t off = (((a_lrow + mi * 16) * RG_RS) + kk + a_lcol) * 2;
                ldmatrix_x4(afh[mi], ahi + off);
                ldmatrix_x4(afl[mi], alo + off);
            }
            #pragma unroll
            for (int pr = 0; pr < 2; pr++) {
                const uint32_t off = (((b_lrow + pr * 16) * RG_RS) + kk + b_lcol) * 2;
                ldmatrix_x4(bfh[pr], bhi + off);
                ldmatrix_x4(bfl[pr], blo + off);
            }
            #pragma unroll
            for (int mi = 0; mi < 4; mi++)
                #pragma unroll
                for (int ni = 0; ni < 4; ni++) {
                    const uint32_t* bh = bfh[ni >> 1] + (ni & 1) * 2;
                    const uint32_t* bl = bfl[ni >> 1] + (ni & 1) * 2;
                    mma_f16(acc[mi][ni], afh[mi], bh);
                    mma_f16(acc[mi][ni], afh[mi], bl);
                    mma_f16(acc[mi][ni], afl[mi], bh);
                }
        }
    };

    // ---- 2-stage pipeline: prefetch 1 tile; wait<0> drains current group ----
    load_stage(0, 0);
    for (int kt = 0; kt < NKT; kt++) {
        cp_wait<0>();
        __syncthreads();
        if (kt + 1 < NKT) load_stage((kt + 1) & 1, kt + 1);
        compute_stage(kt & 1);
    }

    // ---- epilogue: silu -> g_h (fp32) ----
    float bias2[4][2];
    #pragma unroll
    for (int ni = 0; ni < 4; ni++) {
        const int col = col0 + wn * 32 + ni * 8 + c * 2;
        bias2[ni][0] = Rb1[col];
        bias2[ni][1] = Rb1[col + 1];
    }
    #pragma unroll
    for (int mi = 0; mi < 4; mi++) {
        #pragma unroll
        for (int h = 0; h < 2; h++) {
            const int row = row0 + wm * 64 + mi * 16 + r + h * 8;
            float* dst = g_h + (size_t)row * HH;
            #pragma unroll
            for (int ni = 0; ni < 4; ni++) {
                const int col = col0 + wn * 32 + ni * 8 + c * 2;
                const float v0 = silu_precise(acc[mi][ni][h * 2 + 0] + bias2[ni][0]);
                const float v1 = silu_precise(acc[mi][ni][h * 2 + 1] + bias2[ni][1]);
                *(float2*)(dst + col) = make_float2(v0, v1);
            }
        }
    }
}

// ---------------- FP16 mma.sync grouped GEMM, 3-stage cp.async (R16 exact) ---
#define HG_STAGES 3
#define HG_RS 72
#define HG_TILE (128 * HG_RS)
#define HG_TILE_B (HG_TILE * 2)
#define HG_SMEM_BYTES (HG_STAGES * HG_TILE_B * 2)

template <int MODE>
__global__ __launch_bounds__(256, 2)
void hgemm6_kernel(const float* __restrict__ Bias)
{
    constexpr int KPAD = (MODE == 1) ? KP1 : HH;
    constexpr int NN   = (MODE == 3) ? DD : HH;
    constexpr int NKT  = KPAD / 64;

    const int e = blockIdx.z;
    const int m_base  = g_off[e];
    const int m_count = g_cnt[e];
    const int row0 = blockIdx.y * 128;
    if (row0 >= m_count) return;
    const int col0 = blockIdx.x * 128;

    extern __shared__ __half smem[];
    __half* Asm = smem;
    __half* Bsm = smem + HG_STAGES * HG_TILE;

    const int tid  = threadIdx.x;
    const int warp = tid >> 5;
    const int lane = tid & 31;
    const int wm = warp >> 2;
    const int wn = warp & 3;
    const int r  = lane >> 2;
    const int c  = lane & 3;

    const int lrow = tid >> 2;
    const int lc16 = tid & 3;

    const __half* srcA[2];
    uint32_t szA[2];
    const __half* Wg =
        (MODE == 1) ? g_w1t : (MODE == 2) ? g_w2t : g_w3t;
    const __half* Wbase = Wg + (size_t)e * NN * KPAD + (size_t)col0 * KPAD;
    const __half* srcB[2];

    #pragma unroll
    for (int i = 0; i < 2; i++) {
        const int rowi = lrow + i * 64;
        const int rloc = row0 + rowi;
        const bool valid = rloc < m_count;
        const __half* p;
        if (MODE == 1)      p = g_xh + (valid ? (size_t)g_perm[m_base + rloc] * KP1 : 0);
        else if (MODE == 2) p = g_h1 + (valid ? (size_t)(m_base + rloc) * HH : 0);
        else                p = g_h2 + (valid ? (size_t)(m_base + rloc) * HH : 0);
        srcA[i] = p + lc16 * 8;
        szA[i]  = valid ? 16u : 0u;
        srcB[i] = Wbase + (size_t)rowi * KPAD + lc16 * 8;
    }
    const uint32_t dstoff_b[2] = {
        (uint32_t)((lrow * HG_RS + lc16 * 8) * 2),
        (uint32_t)(((lrow + 64) * HG_RS + lc16 * 8) * 2) };

    const uint32_t asm_u32 = smem_u32(Asm);
    const uint32_t bsm_u32 = smem_u32(Bsm);

    auto load_stage = [&](int s, int kt) {
        const uint32_t ab = asm_u32 + s * HG_TILE_B;
        const uint32_t bb = bsm_u32 + s * HG_TILE_B;
        const int koff = kt * 64;
        #pragma unroll
        for (int i = 0; i < 2; i++) {
            cp_async16(ab + dstoff_b[i],      srcA[i] + koff,      szA[i]);
            cp_async16(ab + dstoff_b[i] + 64, srcA[i] + koff + 32, szA[i]);
            cp_async16(bb + dstoff_b[i],      srcB[i] + koff,      16u);
            cp_async16(bb + dstoff_b[i] + 64, srcB[i] + koff + 32, 16u);
        }
        cp_commit();
    };

    float acc[4][4][4];
    #pragma unroll
    for (int mi = 0; mi < 4; mi++)
        #pragma unroll
        for (int ni = 0; ni < 4; ni++)
            #pragma unroll
            for (int q = 0; q < 4; q++) acc[mi][ni][q] = 0.f;

    const int a_lrow = wm * 64 + (lane & 15);
    const int a_lcol = (lane >> 4) * 8;
    const int b_lrow = wn * 32 + ((lane >> 4) & 1) * 8 + (lane & 7);
    const int b_lcol = ((lane >> 3) & 1) * 8;

    auto compute_stage = [&](int s) {
        const uint32_t ab = asm_u32 + s * HG_TILE_B;
        const uint32_t bb = bsm_u32 + s * HG_TILE_B;
        #pragma unroll
        for (int kk = 0; kk < 64; kk += 16) {
            uint32_t af[4][4], bf[2][4];
            #pragma unroll
            for (int mi = 0; mi < 4; mi++)
                ldmatrix_x4(af[mi],
                    ab + (((a_lrow + mi * 16) * HG_RS) + kk + a_lcol) * 2);
            #pragma unroll
            for (int pr = 0; pr < 2; pr++)
                ldmatrix_x4(bf[pr],
                    bb + (((b_lrow + pr * 16) * HG_RS) + kk + b_lcol) * 2);
            #pragma unroll
            for (int mi = 0; mi < 4; mi++)
                #pragma unroll
                for (int ni = 0; ni < 4; ni++)
                    mma_f16(acc[mi][ni], af[mi], bf[ni >> 1] + (ni & 1) * 2);
        }
    };

    load_stage(0, 0);
    if (NKT > 1) load_stage(1, 1);
    else         cp_commit();

    for (int kt = 0; kt < NKT; kt++) {
        cp_wait<1>();
        __syncthreads();
        const int ktn = kt + 2;
        if (ktn < NKT) load_stage(ktn % HG_STAGES, ktn);
        else           cp_commit();
        compute_stage(kt % HG_STAGES);
    }

    const float* Bp = Bias + (size_t)e * NN;
    float bias2[4][2];
    #pragma unroll
    for (int ni = 0; ni < 4; ni++) {
        const int col = col0 + wn * 32 + ni * 8 + c * 2;
        bias2[ni][0] = Bp[col];
        bias2[ni][1] = Bp[col + 1];
    }

    #pragma unroll
    for (int mi = 0; mi < 4; mi++) {
        #pragma unroll
        for (int h = 0; h < 2; h++) {
            const int rloc = row0 + wm * 64 + mi * 16 + r + h * 8;
            if (rloc >= m_count) continue;
            const size_t a_idx = (size_t)(m_base + rloc);
            if (MODE == 3) {
                float* dst = g_eout + a_idx * DD;
                const float scale = g_wgt[a_idx];
                #pragma unroll
                for (int ni = 0; ni < 4; ni++) {
                    const int col = col0 + wn * 32 + ni * 8 + c * 2;
                    const float v0 = (acc[mi][ni][h * 2 + 0] + bias2[ni][0]) * scale;
                    const float v1 = (acc[mi][ni][h * 2 + 1] + bias2[ni][1]) * scale;
                    *(float2*)(dst + col) = make_float2(v0, v1);
                }
            } else {
                __half* dst = ((MODE == 1) ? g_h1 : g_h2) + a_idx * HH;
                #pragma unroll
                for (int ni = 0; ni < 4; ni++) {
                    const int col = col0 + wn * 32 + ni * 8 + c * 2;
                    const float v0 = silu_precise(acc[mi][ni][h * 2 + 0] + bias2[ni][0]);
                    const float v1 = silu_precise(acc[mi][ni][h * 2 + 1] + bias2[ni][1]);
                    *(__half2*)(dst + col) = __floats2half2_rn(v0, v1);
                }
            }
        }
    }
}

// ---------------- router logits + top-2 softmax (exact fp32, unchanged) ------
__global__ __launch_bounds__(256)
void logits_topk_kernel(const float* __restrict__ Rw2, const float* __restrict__ Rb2)
{
    const int warp = (blockIdx.x * (blockDim.x >> 5)) + (threadIdx.x >> 5);
    if (warp >= BB) return;
    const int b = warp;
    const int lane = threadIdx.x & 31;

    float l[EE];
    #pragma unroll
    for (int e = 0; e < EE; e++) l[e] = 0.f;

    const float* __restrict__ hrow = g_h + (size_t)b * HH;
    for (int k = lane; k < HH; k += 32) {
        const float hv = hrow[k];
        const float4 w0 = *(const float4*)(Rw2 + (size_t)k * EE);
        const float4 w1 = *(const float4*)(Rw2 + (size_t)k * EE + 4);
        l[0] = fmaf(hv, w0.x, l[0]);
        l[1] = fmaf(hv, w0.y, l[1]);
        l[2] = fmaf(hv, w0.z, l[2]);
        l[3] = fmaf(hv, w0.w, l[3]);
        l[4] = fmaf(hv, w1.x, l[4]);
        l[5] = fmaf(hv, w1.y, l[5]);
        l[6] = fmaf(hv, w1.z, l[6]);
        l[7] = fmaf(hv, w1.w, l[7]);
    }
    #pragma unroll
    for (int off = 16; off > 0; off >>= 1)
        #pragma unroll
        for (int e = 0; e < EE; e++)
            l[e] += __shfl_xor_sync(0xffffffff, l[e], off);

    if (lane == 0) {
        #pragma unroll
        for (int e = 0; e < EE; e++) l[e] += Rb2[e];
        int i0 = 0;
        #pragma unroll
        for (int e = 1; e < EE; e++) if (l[e] > l[i0]) i0 = e;
        int i1 = (i0 == 0) ? 1 : 0;
        #pragma unroll
        for (int e = 0; e < EE; e++)
            if (e != i0 && l[e] > l[i1]) i1 = e;
        const float e1 = expf(l[i1] - l[i0]);
        const float inv = 1.f / (1.f + e1);
        g_topk_idx[b * 2 + 0] = i0;
        g_topk_idx[b * 2 + 1] = i1;
        g_topk_a[b * 2 + 0] = inv;
        g_topk_a[b * 2 + 1] = e1 * inv;
        atomicAdd(&g_cnt[i0], 1);
        atomicAdd(&g_cnt[i1], 1);
    }
}

// ---------------- bucket offsets ---------------------------------------------
__global__ void scan_kernel()
{
    if (threadIdx.x == 0) {
        int s = 0;
        for (int e = 0; e < EE; e++) {
            g_off[e] = s;
            g_cursor[e] = s;
            s += g_cnt[e];
        }
    }
}

// ---------------- scatter tokens into expert buckets -------------------------
__global__ __launch_bounds__(256)
void scatter_kernel()
{
    const int b = blockIdx.x * blockDim.x + threadIdx.x;
    if (b >= BB) return;
    #pragma unroll
    for (int j = 0; j < TOPK; j++) {
        const int e = g_topk_idx[b * 2 + j];
        const int pos = atomicAdd(&g_cursor[e], 1);
        g_perm[pos] = b;
        g_wgt[pos]  = g_topk_a[b * 2 + j];
        g_slot[b * 2 + j] = pos;
    }
}

// ---------------- deterministic 2-way combine --------------------------------
__global__ __launch_bounds__(256)
void combine_kernel(float* __restrict__ out)
{
    const int idx = blockIdx.x * blockDim.x + threadIdx.x;
    if (idx >= BB * DD / 4) return;
    const int b = idx / (DD / 4);
    const int q = idx % (DD / 4);
    const int s0 = g_slot[b * 2 + 0];
    const int s1 = g_slot[b * 2 + 1];
    const float4 v0 = *((const float4*)g_eout + (size_t)s0 * (DD / 4) + q);
    const float4 v1 = *((const float4*)g_eout + (size_t)s1 * (DD / 4) + q);
    ((float4*)out)[idx] = make_float4(v0.x + v1.x, v0.y + v1.y, v0.z + v1.z, v0.w + v1.w);
}

// ---------------- launch -----------------------------------------------------
extern "C" void kernel_launch(void* const* d_in, const int* in_sizes, int n_in,
                              void* d_out, int out_size)
{
    const float* t   = (const float*)d_in[0];
    const float* x   = (const float*)d_in[1];
    const float* Rw1 = (const float*)d_in[2];
    const float* Rb1 = (const float*)d_in[3];
    const float* Rw2 = (const float*)d_in[4];
    const float* Rb2 = (const float*)d_in[5];
    const float* Ew1 = (const float*)d_in[6];
    const float* Eb1 = (const float*)d_in[7];
    const float* Ew2 = (const float*)d_in[8];
    const float* Eb2 = (const float*)d_in[9];
    const float* Ew3 = (const float*)d_in[10];
    const float* Eb3 = (const float*)d_in[11];
    float* out = (float*)d_out;

    cudaFuncSetAttribute(router_split_kernel, cudaFuncAttributeMaxDynamicSharedMemorySize, RG_SMEM_BYTES);
    cudaFuncSetAttribute(hgemm6_kernel<1>, cudaFuncAttributeMaxDynamicSharedMemorySize, HG_SMEM_BYTES);
    cudaFuncSetAttribute(hgemm6_kernel<2>, cudaFuncAttributeMaxDynamicSharedMemorySize, HG_SMEM_BYTES);
    cudaFuncSetAttribute(hgemm6_kernel<3>, cudaFuncAttributeMaxDynamicSharedMemorySize, HG_SMEM_BYTES);

    reset_kernel<<<1, 32>>>();

    // pre-pass: split/pack inputs + weight conversions (device-side dests)
    pack_x_split_kernel<<<(BB * KP1 + 255) / 256, 256>>>(x, t);
    convert_r1_kernel<<<dim3(HH / 32, KP1 / 32), dim3(32, 8)>>>(Rw1);
    convert_w_kernel<1><<<dim3(HH / 32, KP1 / 32, EE), dim3(32, 8)>>>(Ew1, KXT, HH, KP1);
    convert_w_kernel<2><<<dim3(HH / 32, HH / 32, EE), dim3(32, 8)>>>(Ew2, HH, HH, HH);
    convert_w_kernel<3><<<dim3(DD / 32, HH / 32, EE), dim3(32, 8)>>>(Ew3, HH, DD, HH);

    // router hidden: split-fp16 tensor-core GEMM (~fp32 accurate)
    router_split_kernel<<<dim3(HH / 128, BB / 128), 256, RG_SMEM_BYTES>>>(Rb1);

    // logits + top-2 softmax gate (exact fp32)
    logits_topk_kernel<<<BB / 8, 256>>>(Rw2, Rb2);
    scan_kernel<<<1, 32>>>();
    scatter_kernel<<<BB / 256, 256>>>();

    // grouped expert MLP: fp16 mma.sync + ldmatrix + 3-stage cp.async
    hgemm6_kernel<1><<<dim3(HH / 128, 256, EE), 256, HG_SMEM_BYTES>>>(Eb1);
    hgemm6_kernel<2><<<dim3(HH / 128, 256, EE), 256, HG_SMEM_BYTES>>>(Eb2);
    hgemm6_kernel<3><<<dim3(DD / 128, 256, EE), 256, HG_SMEM_BYTES>>>(Eb3);

    // out[b] = alpha0*eout[slot0] + alpha1*eout[slot1]
    combine_kernel<<<(BB * DD / 4 + 255) / 256, 256>>>(out);
}